// round 1
// baseline (speedup 1.0000x reference)
#include <cuda_runtime.h>
#include <cstdint>

#define BB   128
#define TT   512
#define II   300
#define HH   150
#define G3   450
#define KK   6
#define CC   300
#define THD  20
#define CLS  5
#define JS   320   // Whh^T columns resident in smem for the scan

// ---------------- scratch (static device globals; no runtime allocation) ----------------
__device__ float d_gi_f[(size_t)BB * TT * G3];     // 118 MB
__device__ float d_gi_b[(size_t)BB * TT * G3];     // 118 MB
__device__ float d_seq [(size_t)BB * TT * 2 * HH]; // 78.6 MB
__device__ float d_hidden[BB * 2 * HH];
__device__ float d_WT_f[HH * G3];
__device__ float d_WT_b[HH * G3];
__device__ float d_bias2[KK * 2 * HH];
__device__ float d_context[BB * KK * 2 * HH];
__device__ float d_pooled [BB * KK * 2 * HH];

// ---------------- prep: transpose Whh (450x150 -> 150x450) for coalesced scan loads ----
__global__ void prep_kernel(const float* __restrict__ Whh_f, const float* __restrict__ Whh_b) {
    int idx = blockIdx.x * blockDim.x + threadIdx.x;
    if (idx < HH * G3) {
        int i = idx / G3, j = idx - i * G3;
        d_WT_f[idx] = Whh_f[j * HH + i];
        d_WT_b[idx] = Whh_b[j * HH + i];
    }
}

// ---------------- bias2[k][d] = battn[k][d] + sum_c attn_context[k][c] * Wattn[k][c][d] --
__global__ void bias2_kernel(const float* __restrict__ ac, const float* __restrict__ Wattn,
                             const float* __restrict__ battn) {
    int k = blockIdx.x;
    __shared__ float as[CC];
    int tid = threadIdx.x;
    if (tid < CC) as[tid] = ac[k * CC + tid];
    __syncthreads();
    if (tid < 2 * HH) {
        float acc = battn[k * 2 * HH + tid];
        const float* w = Wattn + (size_t)k * (CC + 2 * HH) * (2 * HH) + tid;
        #pragma unroll 4
        for (int c = 0; c < CC; ++c) acc += as[c] * w[(size_t)c * (2 * HH)];
        d_bias2[k * 2 * HH + tid] = acc;
    }
}

// ---------------- gi GEMM: O[m][n] = bih[n] + sum_k X[m][k]*W[n][k] ---------------------
// M=65536, N=450 (tiled to 512 with mask), K=300. BM=128 BN=64 BK=16, 256 thr, TM=8 TN=4.
__global__ void gemm_gi(const float* __restrict__ X, const float* __restrict__ W,
                        const float* __restrict__ bias, int which) {
    __shared__ float As[16][128];
    __shared__ float Bs[16][64];
    float* O = which ? d_gi_b : d_gi_f;
    int m0 = blockIdx.y * 128;
    int n0 = blockIdx.x * 64;
    int tid = threadIdx.x;
    int tx = tid & 15, ty = tid >> 4;
    float acc[8][4];
    #pragma unroll
    for (int i = 0; i < 8; ++i)
        #pragma unroll
        for (int j = 0; j < 4; ++j) acc[i][j] = 0.f;

    int am = tid >> 1, ak = (tid & 1) * 8;
    int bn = tid >> 2, bk = (tid & 3) * 4;

    for (int k0 = 0; k0 < II; k0 += 16) {
        #pragma unroll
        for (int u = 0; u < 8; ++u) {
            int k = k0 + ak + u;
            As[ak + u][am] = (k < II) ? X[(size_t)(m0 + am) * II + k] : 0.f;
        }
        int n = n0 + bn;
        #pragma unroll
        for (int u = 0; u < 4; ++u) {
            int k = k0 + bk + u;
            Bs[bk + u][bn] = (k < II && n < G3) ? W[(size_t)n * II + k] : 0.f;
        }
        __syncthreads();
        #pragma unroll
        for (int kk = 0; kk < 16; ++kk) {
            const float4* a4 = reinterpret_cast<const float4*>(&As[kk][ty * 8]);
            float4 av0 = a4[0], av1 = a4[1];
            float4 bv = *reinterpret_cast<const float4*>(&Bs[kk][tx * 4]);
            float a[8] = {av0.x, av0.y, av0.z, av0.w, av1.x, av1.y, av1.z, av1.w};
            float b[4] = {bv.x, bv.y, bv.z, bv.w};
            #pragma unroll
            for (int i = 0; i < 8; ++i)
                #pragma unroll
                for (int j = 0; j < 4; ++j) acc[i][j] = fmaf(a[i], b[j], acc[i][j]);
        }
        __syncthreads();
    }
    #pragma unroll
    for (int i = 0; i < 8; ++i) {
        int m = m0 + ty * 8 + i;
        #pragma unroll
        for (int j = 0; j < 4; ++j) {
            int n = n0 + tx * 4 + j;
            if (n < G3) O[(size_t)m * G3 + n] = acc[i][j] + bias[n];
        }
    }
}

// ---------------- persistent bidirectional GRU scan -------------------------------------
// 128 blocks: blocks 0..63 forward (2 batch rows each), 64..127 backward.
// Whh^T columns [0,JS) in smem, [JS,450) streamed from L2 (stays L2-resident).
__device__ __forceinline__ float sigm(float x) { return 1.f / (1.f + __expf(-x)); }

__global__ void scan_kernel(const float* __restrict__ bhh_f, const float* __restrict__ bhh_b) {
    extern __shared__ float sm[];
    float* Wsh = sm;                    // HH * JS
    float* hb  = sm + HH * JS;          // 2 * 152
    float* ghb = hb + 2 * 152;          // 2 * 452
    float* bsm = ghb + 2 * 452;         // 452

    int bb  = blockIdx.x;
    int dir = bb >> 6;
    int p   = bb & 63;
    int b0  = 2 * p, b1 = b0 + 1;
    const float* gi  = dir ? d_gi_b : d_gi_f;
    const float* WT  = dir ? d_WT_b : d_WT_f;
    const float* bhh = dir ? bhh_b : bhh_f;
    int tid = threadIdx.x;              // 256

    for (int idx = tid; idx < HH * JS; idx += 256) {
        int i = idx / JS, j = idx - i * JS;
        Wsh[idx] = WT[i * G3 + j];
    }
    for (int idx = tid; idx < 2 * 152; idx += 256) hb[idx] = 0.f;
    for (int idx = tid; idx < G3; idx += 256) bsm[idx] = bhh[idx];
    __syncthreads();

    const int jA = tid, jB = tid + 256;
    const bool BinS  = (jB < JS);
    const bool Bval  = (jB < G3);

    // gate-stage element mapping: e1 = tid (always <300), e2 = tid+256 (<300 for tid<44)
    int e1 = tid;            int eb1 = e1 / HH, ej1 = e1 - eb1 * HH;
    int e2 = tid + 256;      bool has2 = (e2 < 2 * HH);
    int eb2 = e2 / HH, ej2 = e2 - eb2 * HH;

    for (int s = 0; s < TT; ++s) {
        int t = dir ? (TT - 1 - s) : s;
        // prefetch gi rows for this step (hidden under the matvec)
        size_t base0 = ((size_t)b0 * TT + t) * G3;
        size_t base1 = ((size_t)b1 * TT + t) * G3;
        size_t ge1 = (eb1 ? base1 : base0) + ej1;
        float g1r = gi[ge1], g1z = gi[ge1 + HH], g1n = gi[ge1 + 2 * HH];
        float g2r = 0.f, g2z = 0.f, g2n = 0.f;
        if (has2) {
            size_t ge2 = (eb2 ? base1 : base0) + ej2;
            g2r = gi[ge2]; g2z = gi[ge2 + HH]; g2n = gi[ge2 + 2 * HH];
        }

        // matvec: gh[b][j] = bhh[j] + sum_i Whh[j][i]*h[b][i]
        float aA0 = bsm[jA], aA1 = aA0;
        float aB0 = 0.f, aB1 = 0.f;
        if (BinS) {
            aB0 = bsm[jB]; aB1 = aB0;
            #pragma unroll 10
            for (int i = 0; i < HH; ++i) {
                float h0 = hb[i], h1 = hb[152 + i];
                float wA = Wsh[i * JS + jA];
                aA0 = fmaf(wA, h0, aA0); aA1 = fmaf(wA, h1, aA1);
                float wB = Wsh[i * JS + jB];
                aB0 = fmaf(wB, h0, aB0); aB1 = fmaf(wB, h1, aB1);
            }
        } else {
            if (Bval) { aB0 = bsm[jB]; aB1 = aB0; }
            const float* wp = WT + jB;
            #pragma unroll 10
            for (int i = 0; i < HH; ++i) {
                float h0 = hb[i], h1 = hb[152 + i];
                float wA = Wsh[i * JS + jA];
                aA0 = fmaf(wA, h0, aA0); aA1 = fmaf(wA, h1, aA1);
                float wB = Bval ? wp[i * G3] : 0.f;
                aB0 = fmaf(wB, h0, aB0); aB1 = fmaf(wB, h1, aB1);
            }
        }
        ghb[jA] = aA0; ghb[452 + jA] = aA1;
        if (Bval) { ghb[jB] = aB0; ghb[452 + jB] = aB1; }
        __syncthreads();

        // gates + h update + seq write
        {
            float hr = ghb[eb1 * 452 + ej1];
            float hz = ghb[eb1 * 452 + HH + ej1];
            float hn = ghb[eb1 * 452 + 2 * HH + ej1];
            float r = sigm(g1r + hr);
            float z = sigm(g1z + hz);
            float n = tanhf(g1n + r * hn);
            float hp = hb[eb1 * 152 + ej1];
            float hv = (1.f - z) * n + z * hp;
            hb[eb1 * 152 + ej1] = hv;
            d_seq[((size_t)(eb1 ? b1 : b0) * TT + t) * (2 * HH) + dir * HH + ej1] = hv;
        }
        if (has2) {
            float hr = ghb[eb2 * 452 + ej2];
            float hz = ghb[eb2 * 452 + HH + ej2];
            float hn = ghb[eb2 * 452 + 2 * HH + ej2];
            float r = sigm(g2r + hr);
            float z = sigm(g2z + hz);
            float n = tanhf(g2n + r * hn);
            float hp = hb[eb2 * 152 + ej2];
            float hv = (1.f - z) * n + z * hp;
            hb[eb2 * 152 + ej2] = hv;
            d_seq[((size_t)(eb2 ? b1 : b0) * TT + t) * (2 * HH) + dir * HH + ej2] = hv;
        }
        __syncthreads();
    }
    // final hidden state
    d_hidden[(size_t)(eb1 ? b1 : b0) * (2 * HH) + dir * HH + ej1] = hb[eb1 * 152 + ej1];
    if (has2)
        d_hidden[(size_t)(eb2 ? b1 : b0) * (2 * HH) + dir * HH + ej2] = hb[eb2 * 152 + ej2];
}

// ---------------- context[b][k][d] = tanh(bias2[k][d] + sum_h hidden[b][h]*Wattn[k][C+h][d])
__global__ void ctx_kernel(const float* __restrict__ Wattn) {
    int bk = blockIdx.x;
    int b = bk / KK, k = bk - b * KK;
    __shared__ float hs[2 * HH];
    int tid = threadIdx.x; // 320
    if (tid < 2 * HH) hs[tid] = d_hidden[b * 2 * HH + tid];
    __syncthreads();
    if (tid < 2 * HH) {
        float acc = d_bias2[k * 2 * HH + tid];
        const float* w = Wattn + ((size_t)k * (CC + 2 * HH) + CC) * (2 * HH) + tid;
        #pragma unroll 4
        for (int c = 0; c < 2 * HH; ++c) acc += hs[c] * w[(size_t)c * (2 * HH)];
        d_context[((size_t)b * KK + k) * (2 * HH) + tid] = tanhf(acc);
    }
}

// ---------------- energy -> softmax(t) -> pooled, fused per batch row --------------------
__global__ void pool_kernel() {
    int b = blockIdx.x;
    __shared__ float ctx[KK][2 * HH];
    __shared__ float en[TT][KK];
    int tid = threadIdx.x;              // 256
    int w = tid >> 5, lane = tid & 31;
    for (int i = tid; i < KK * 2 * HH; i += 256)
        ctx[i / (2 * HH)][i % (2 * HH)] = d_context[(size_t)b * KK * 2 * HH + i];
    __syncthreads();
    // energy[t][k]
    for (int t = w; t < TT; t += 8) {
        const float* srow = d_seq + ((size_t)b * TT + t) * (2 * HH);
        float pk[KK] = {0, 0, 0, 0, 0, 0};
        for (int d = lane; d < 2 * HH; d += 32) {
            float s = srow[d];
            #pragma unroll
            for (int k = 0; k < KK; ++k) pk[k] = fmaf(s, ctx[k][d], pk[k]);
        }
        #pragma unroll
        for (int k = 0; k < KK; ++k) {
            float v = pk[k];
            for (int off = 16; off; off >>= 1) v += __shfl_xor_sync(~0u, v, off);
            if (lane == 0) en[t][k] = v;
        }
    }
    __syncthreads();
    // softmax over t, one warp per k
    if (w < KK) {
        float mx = -1e30f;
        for (int t = lane; t < TT; t += 32) mx = fmaxf(mx, en[t][w]);
        for (int off = 16; off; off >>= 1) mx = fmaxf(mx, __shfl_xor_sync(~0u, mx, off));
        float sum = 0.f;
        for (int t = lane; t < TT; t += 32) { float e = __expf(en[t][w] - mx); en[t][w] = e; sum += e; }
        for (int off = 16; off; off >>= 1) sum += __shfl_xor_sync(~0u, sum, off);
        float inv = 1.f / sum;
        for (int t = lane; t < TT; t += 32) en[t][w] *= inv;
    }
    __syncthreads();
    // pooled[b][k][d] = sum_t seq[b][t][d] * probs[t][k]
    for (int d = tid; d < 2 * HH; d += 256) {
        float acc[KK] = {0, 0, 0, 0, 0, 0};
        for (int t = 0; t < TT; ++t) {
            float s = d_seq[((size_t)b * TT + t) * (2 * HH) + d];
            #pragma unroll
            for (int k = 0; k < KK; ++k) acc[k] = fmaf(s, en[t][k], acc[k]);
        }
        #pragma unroll
        for (int k = 0; k < KK; ++k)
            d_pooled[((size_t)b * KK + k) * (2 * HH) + d] = acc[k];
    }
}

// ---------------- topic -> feats -> logits -> softmax output -----------------------------
__global__ void topic_kernel(const float* __restrict__ Wtop, const float* __restrict__ btop,
                             const float* __restrict__ Wout, const float* __restrict__ bout,
                             float* __restrict__ out) {
    int b = blockIdx.x;
    __shared__ float ps[KK * 2 * HH];
    __shared__ float feats[KK * THD];
    __shared__ float lg[CLS];
    int tid = threadIdx.x; // 128
    for (int i = tid; i < KK * 2 * HH; i += 128) ps[i] = d_pooled[(size_t)b * KK * 2 * HH + i];
    __syncthreads();
    if (tid < KK * THD) {
        int k = tid / THD, th = tid - k * THD;
        float acc = btop[tid];
        const float* wp = Wtop + (size_t)k * (2 * HH) * THD + th;
        #pragma unroll 4
        for (int d = 0; d < 2 * HH; ++d) acc += ps[k * 2 * HH + d] * wp[d * THD];
        feats[tid] = fmaxf(acc, 0.f);
    }
    __syncthreads();
    if (tid < CLS) {
        float acc = bout[tid];
        for (int e = 0; e < KK * THD; ++e) acc += feats[e] * Wout[e * CLS + tid];
        lg[tid] = acc;
    }
    __syncthreads();
    if (tid < CLS) {
        float mx = lg[0];
        #pragma unroll
        for (int c = 1; c < CLS; ++c) mx = fmaxf(mx, lg[c]);
        float sum = 0.f;
        #pragma unroll
        for (int c = 0; c < CLS; ++c) sum += __expf(lg[c] - mx);
        out[b * CLS + tid] = __expf(lg[tid] - mx) / sum;
    }
}

// ---------------- orthogonality regularizer ----------------------------------------------
__global__ void reg_kernel(float* __restrict__ regout) {
    __shared__ float cs[KK * 2 * HH];
    __shared__ float D[KK * KK];
    __shared__ float acc;
    int tid = threadIdx.x; // 256
    int w = tid >> 5, lane = tid & 31;
    if (tid == 0) acc = 0.f;
    for (int b = 0; b < BB; ++b) {
        __syncthreads();
        for (int i = tid; i < KK * 2 * HH; i += 256) cs[i] = d_context[(size_t)b * KK * 2 * HH + i];
        __syncthreads();
        for (int p = w; p < KK * KK; p += 8) {
            int k = p / KK, j = p - k * KK;
            float v = 0.f;
            for (int d = lane; d < 2 * HH; d += 32) v += cs[k * 2 * HH + d] * cs[j * 2 * HH + d];
            for (int off = 16; off; off >>= 1) v += __shfl_xor_sync(~0u, v, off);
            if (lane == 0) D[p] = v;
        }
        __syncthreads();
        if (tid == 0) {
            float nk[KK];
            #pragma unroll
            for (int k = 0; k < KK; ++k) nk[k] = fmaxf(sqrtf(D[k * KK + k]), 1e-12f);
            float S = 0.f;
            for (int k = 0; k < KK; ++k)
                for (int j = 0; j < KK; ++j) {
                    float g = D[k * KK + j] / (nk[k] * nk[j]) - (k == j ? 1.f : 0.f);
                    S += g * g;
                }
            acc += sqrtf(S);
        }
    }
    __syncthreads();
    if (tid == 0) *regout = acc / (float)BB;
}

// ---------------- launch ------------------------------------------------------------------
extern "C" void kernel_launch(void* const* d_in, const int* in_sizes, int n_in,
                              void* d_out, int out_size) {
    const float* x      = (const float*)d_in[0];
    const float* Wih_f  = (const float*)d_in[1];
    const float* Whh_f  = (const float*)d_in[2];
    const float* bih_f  = (const float*)d_in[3];
    const float* bhh_f  = (const float*)d_in[4];
    const float* Wih_b  = (const float*)d_in[5];
    const float* Whh_b  = (const float*)d_in[6];
    const float* bih_b  = (const float*)d_in[7];
    const float* bhh_b  = (const float*)d_in[8];
    const float* attn_c = (const float*)d_in[9];
    const float* Wattn  = (const float*)d_in[10];
    const float* battn  = (const float*)d_in[11];
    const float* Wtop   = (const float*)d_in[12];
    const float* btop   = (const float*)d_in[13];
    const float* Wout   = (const float*)d_in[14];
    const float* bout   = (const float*)d_in[15];
    float* out = (float*)d_out;

    const int scan_smem = (HH * JS + 2 * 152 + 2 * 452 + 452) * (int)sizeof(float); // ~198.6 KB
    cudaFuncSetAttribute(scan_kernel, cudaFuncAttributeMaxDynamicSharedMemorySize, scan_smem);

    prep_kernel<<<(HH * G3 + 255) / 256, 256>>>(Whh_f, Whh_b);
    bias2_kernel<<<KK, 320>>>(attn_c, Wattn, battn);

    gemm_gi<<<dim3(8, 512), 256>>>(x, Wih_f, bih_f, 0);
    gemm_gi<<<dim3(8, 512), 256>>>(x, Wih_b, bih_b, 1);

    scan_kernel<<<128, 256, scan_smem>>>(bhh_f, bhh_b);

    ctx_kernel<<<BB * KK, 320>>>(Wattn);
    pool_kernel<<<BB, 256>>>();
    topic_kernel<<<BB, 128>>>(Wtop, btop, Wout, bout, out);
    if (out_size > BB * CLS) reg_kernel<<<1, 256>>>(out + BB * CLS);
}

// round 2
// speedup vs baseline: 2.5961x; 2.5961x over previous
#include <cuda_runtime.h>
#include <cuda_fp16.h>
#include <cstdint>

#define BB   128
#define TT   512
#define II   300
#define HH   150
#define G3   450
#define KK   6
#define CC   300
#define THD  20
#define CLS  5

#define NPAIR 225          // 450/2 j-pairs
#define WPAD  156          // half2 words per jpair row (150 used, padded; conflict-free)

// ---------------- scratch ----------------
__device__ float d_gi_f[(size_t)BB * TT * G3];
__device__ float d_gi_b[(size_t)BB * TT * G3];
__device__ float d_seq [(size_t)BB * TT * 2 * HH];
__device__ float d_hidden[BB * 2 * HH];
__device__ __half2 d_Wh_f[NPAIR * WPAD];
__device__ __half2 d_Wh_b[NPAIR * WPAD];
__device__ float d_bias2[KK * 2 * HH];
__device__ float d_context[BB * KK * 2 * HH];
__device__ float d_pooled [BB * KK * 2 * HH];
__device__ float d_regpart[BB];

// ---------------- prep: Whh -> packed half2 [jpair][i], zero-padded ----------------
__global__ void prep_kernel(const float* __restrict__ Whh_f, const float* __restrict__ Whh_b) {
    int idx = blockIdx.x * blockDim.x + threadIdx.x;
    int tot = NPAIR * WPAD;
    if (idx < 2 * tot) {
        int d = idx / tot;
        int r = idx - d * tot;
        int t = r / WPAD, c = r - t * WPAD;
        const float* W = d ? Whh_b : Whh_f;
        float lo = 0.f, hi = 0.f;
        if (c < HH) {
            lo = W[(2 * t) * HH + c];
            hi = W[(2 * t + 1) * HH + c];
        }
        __half2 v = __floats2half2_rn(lo, hi);
        if (d) d_Wh_b[r] = v; else d_Wh_f[r] = v;
    }
}

// ---------------- bias2[k][d] = battn[k][d] + sum_c attn_context[k][c] * Wattn[k][c][d] --
__global__ void bias2_kernel(const float* __restrict__ ac, const float* __restrict__ Wattn,
                             const float* __restrict__ battn) {
    int k = blockIdx.x;
    __shared__ float as[CC];
    int tid = threadIdx.x;
    if (tid < CC) as[tid] = ac[k * CC + tid];
    __syncthreads();
    if (tid < 2 * HH) {
        float acc = battn[k * 2 * HH + tid];
        const float* w = Wattn + (size_t)k * (CC + 2 * HH) * (2 * HH) + tid;
        #pragma unroll 4
        for (int c = 0; c < CC; ++c) acc += as[c] * w[(size_t)c * (2 * HH)];
        d_bias2[k * 2 * HH + tid] = acc;
    }
}

// ---------------- gi GEMM: O[m][n] = bih[n] + sum_k X[m][k]*W[n][k] ---------------------
// BM=128 BN=128 BK=8, 256 threads, 8x8 per thread.
__global__ void gemm_gi(const float* __restrict__ X, const float* __restrict__ W,
                        const float* __restrict__ bias, int which) {
    __shared__ float As[8][128];
    __shared__ float Bs[8][128];
    float* O = which ? d_gi_b : d_gi_f;
    int m0 = blockIdx.y * 128;
    int n0 = blockIdx.x * 128;
    int tid = threadIdx.x;
    int tx = tid & 15, ty = tid >> 4;

    float acc[8][8];
    #pragma unroll
    for (int i = 0; i < 8; ++i)
        #pragma unroll
        for (int j = 0; j < 8; ++j) acc[i][j] = 0.f;

    int lr = tid & 127;          // row within tile (A: m-row, B: n-row)
    int kq = (tid >> 7) * 4;     // 0 or 4
    const float* Xr = X + (size_t)(m0 + lr) * II;
    int nB = n0 + lr;
    const float* Wr = W + (size_t)(nB < G3 ? nB : 0) * II;
    bool nok = (nB < G3);

    for (int k0 = 0; k0 < II; k0 += 8) {
        int ka = k0 + kq;
        float4 av = (ka < II) ? *reinterpret_cast<const float4*>(Xr + ka)
                              : make_float4(0.f, 0.f, 0.f, 0.f);
        float4 bv = (nok && ka < II) ? *reinterpret_cast<const float4*>(Wr + ka)
                                     : make_float4(0.f, 0.f, 0.f, 0.f);
        As[kq + 0][lr] = av.x; As[kq + 1][lr] = av.y;
        As[kq + 2][lr] = av.z; As[kq + 3][lr] = av.w;
        Bs[kq + 0][lr] = bv.x; Bs[kq + 1][lr] = bv.y;
        Bs[kq + 2][lr] = bv.z; Bs[kq + 3][lr] = bv.w;
        __syncthreads();
        #pragma unroll
        for (int kk = 0; kk < 8; ++kk) {
            float a[8], b[8];
            *reinterpret_cast<float4*>(a)     = *reinterpret_cast<const float4*>(&As[kk][ty * 8]);
            *reinterpret_cast<float4*>(a + 4) = *reinterpret_cast<const float4*>(&As[kk][ty * 8 + 4]);
            *reinterpret_cast<float4*>(b)     = *reinterpret_cast<const float4*>(&Bs[kk][tx * 8]);
            *reinterpret_cast<float4*>(b + 4) = *reinterpret_cast<const float4*>(&Bs[kk][tx * 8 + 4]);
            #pragma unroll
            for (int i = 0; i < 8; ++i)
                #pragma unroll
                for (int j = 0; j < 8; ++j) acc[i][j] = fmaf(a[i], b[j], acc[i][j]);
        }
        __syncthreads();
    }
    #pragma unroll
    for (int i = 0; i < 8; ++i) {
        int m = m0 + ty * 8 + i;
        float* Orow = O + (size_t)m * G3;
        #pragma unroll
        for (int j = 0; j < 8; j += 2) {
            int n = n0 + tx * 8 + j;
            if (n < G3) {
                float2 v = make_float2(acc[i][j] + bias[n], acc[i][j + 1] + bias[n + 1]);
                *reinterpret_cast<float2*>(Orow + n) = v;
            }
        }
    }
}

// ---------------- persistent bidirectional GRU scan -------------------------------------
// 128 blocks: 0..63 forward (2 batch rows each), 64..127 backward.
// ALL Whh weights resident in smem as half2 (fp32 accumulation).
__device__ __forceinline__ float sigm(float x) { return 1.f / (1.f + __expf(-x)); }

__global__ void scan_kernel(const float* __restrict__ bhh_f, const float* __restrict__ bhh_b) {
    extern __shared__ char smraw[];
    __half2* Wsh = reinterpret_cast<__half2*>(smraw);                 // NPAIR*WPAD
    float* hb0 = reinterpret_cast<float*>(smraw + NPAIR * WPAD * 4);  // 152
    float* hb1 = hb0 + 152;                                           // 152
    float* ghb = hb1 + 152;                                           // 2*452
    float* bsm = ghb + 2 * 452;                                       // 452

    int bb  = blockIdx.x;
    int dir = bb >> 6;
    int p   = bb & 63;
    int b0  = 2 * p, b1 = b0 + 1;
    const float*  gi  = dir ? d_gi_b : d_gi_f;
    const __half2* Wg = dir ? d_Wh_b : d_Wh_f;
    const float* bhh  = dir ? bhh_b : bhh_f;
    int tid = threadIdx.x;              // 256

    for (int idx = tid; idx < NPAIR * WPAD; idx += 256) Wsh[idx] = Wg[idx];
    for (int idx = tid; idx < 2 * 152; idx += 256) hb0[idx] = 0.f;  // hb0+hb1 contiguous
    for (int idx = tid; idx < G3; idx += 256) bsm[idx] = bhh[idx];
    __syncthreads();

    const int jp = tid;
    const bool act = (jp < NPAIR);

    // gate-stage mapping: e1 = tid (0..255), e2 = tid+256 (<300 for tid<44)
    int e1 = tid;            int eb1 = e1 / HH, ej1 = e1 - eb1 * HH;
    int e2 = tid + 256;      bool has2 = (e2 < 2 * HH);
    int eb2 = e2 / HH, ej2 = e2 - eb2 * HH;

    float bs0 = 0.f, bs1 = 0.f;
    if (act) { bs0 = bsm[2 * jp]; bs1 = bsm[2 * jp + 1]; }

    for (int s = 0; s < TT; ++s) {
        int t = dir ? (TT - 1 - s) : s;
        // prefetch gi rows for this step (hidden under the matvec)
        size_t base0 = ((size_t)b0 * TT + t) * G3;
        size_t base1 = ((size_t)b1 * TT + t) * G3;
        size_t ge1 = (eb1 ? base1 : base0) + ej1;
        float g1r = gi[ge1], g1z = gi[ge1 + HH], g1n = gi[ge1 + 2 * HH];
        float g2r = 0.f, g2z = 0.f, g2n = 0.f;
        if (has2) {
            size_t ge2 = (eb2 ? base1 : base0) + ej2;
            g2r = gi[ge2]; g2z = gi[ge2 + HH]; g2n = gi[ge2 + 2 * HH];
        }

        if (act) {
            float a00 = bs0, a01 = bs1;   // row0: j0, j1
            float a10 = bs0, a11 = bs1;   // row1: j0, j1
            const float4* wrow = reinterpret_cast<const float4*>(Wsh + jp * WPAD);
            #pragma unroll
            for (int c = 0; c < 38; ++c) {
                float4 wv = wrow[c];
                float4 h0 = *reinterpret_cast<const float4*>(hb0 + c * 4);
                float4 h1 = *reinterpret_cast<const float4*>(hb1 + c * 4);
                const __half2* wh = reinterpret_cast<const __half2*>(&wv);
                float2 f;
                f = __half22float2(wh[0]);
                a00 = fmaf(f.x, h0.x, a00); a01 = fmaf(f.y, h0.x, a01);
                a10 = fmaf(f.x, h1.x, a10); a11 = fmaf(f.y, h1.x, a11);
                f = __half22float2(wh[1]);
                a00 = fmaf(f.x, h0.y, a00); a01 = fmaf(f.y, h0.y, a01);
                a10 = fmaf(f.x, h1.y, a10); a11 = fmaf(f.y, h1.y, a11);
                f = __half22float2(wh[2]);
                a00 = fmaf(f.x, h0.z, a00); a01 = fmaf(f.y, h0.z, a01);
                a10 = fmaf(f.x, h1.z, a10); a11 = fmaf(f.y, h1.z, a11);
                f = __half22float2(wh[3]);
                a00 = fmaf(f.x, h0.w, a00); a01 = fmaf(f.y, h0.w, a01);
                a10 = fmaf(f.x, h1.w, a10); a11 = fmaf(f.y, h1.w, a11);
            }
            *reinterpret_cast<float2*>(&ghb[2 * jp])       = make_float2(a00, a01);
            *reinterpret_cast<float2*>(&ghb[452 + 2 * jp]) = make_float2(a10, a11);
        }
        __syncthreads();

        // gates + h update + seq write
        {
            float hr = ghb[eb1 * 452 + ej1];
            float hz = ghb[eb1 * 452 + HH + ej1];
            float hn = ghb[eb1 * 452 + 2 * HH + ej1];
            float r = sigm(g1r + hr);
            float z = sigm(g1z + hz);
            float n = tanhf(g1n + r * hn);
            float* hbp = eb1 ? hb1 : hb0;
            float hp = hbp[ej1];
            float hv = (1.f - z) * n + z * hp;
            hbp[ej1] = hv;
            d_seq[((size_t)(eb1 ? b1 : b0) * TT + t) * (2 * HH) + dir * HH + ej1] = hv;
        }
        if (has2) {
            float hr = ghb[eb2 * 452 + ej2];
            float hz = ghb[eb2 * 452 + HH + ej2];
            float hn = ghb[eb2 * 452 + 2 * HH + ej2];
            float r = sigm(g2r + hr);
            float z = sigm(g2z + hz);
            float n = tanhf(g2n + r * hn);
            float* hbp = eb2 ? hb1 : hb0;
            float hp = hbp[ej2];
            float hv = (1.f - z) * n + z * hp;
            hbp[ej2] = hv;
            d_seq[((size_t)(eb2 ? b1 : b0) * TT + t) * (2 * HH) + dir * HH + ej2] = hv;
        }
        __syncthreads();
    }
    {
        float* hbp = eb1 ? hb1 : hb0;
        d_hidden[(size_t)(eb1 ? b1 : b0) * (2 * HH) + dir * HH + ej1] = hbp[ej1];
    }
    if (has2) {
        float* hbp = eb2 ? hb1 : hb0;
        d_hidden[(size_t)(eb2 ? b1 : b0) * (2 * HH) + dir * HH + ej2] = hbp[ej2];
    }
}

// ---------------- context[b][k][d] = tanh(bias2[k][d] + sum_h hidden[b][h]*Wattn[k][C+h][d])
__global__ void ctx_kernel(const float* __restrict__ Wattn) {
    int bk = blockIdx.x;
    int b = bk / KK, k = bk - b * KK;
    __shared__ float hs[2 * HH];
    int tid = threadIdx.x; // 320
    if (tid < 2 * HH) hs[tid] = d_hidden[b * 2 * HH + tid];
    __syncthreads();
    if (tid < 2 * HH) {
        float acc = d_bias2[k * 2 * HH + tid];
        const float* w = Wattn + ((size_t)k * (CC + 2 * HH) + CC) * (2 * HH) + tid;
        #pragma unroll 4
        for (int c = 0; c < 2 * HH; ++c) acc += hs[c] * w[(size_t)c * (2 * HH)];
        d_context[((size_t)b * KK + k) * (2 * HH) + tid] = tanhf(acc);
    }
}

// ---------------- energy -> softmax(t) -> pooled, fused per batch row --------------------
__global__ void pool_kernel() {
    int b = blockIdx.x;
    __shared__ float ctx[KK][2 * HH];
    __shared__ float en[TT][KK];
    int tid = threadIdx.x;              // 256
    int w = tid >> 5, lane = tid & 31;
    for (int i = tid; i < KK * 2 * HH; i += 256)
        ctx[i / (2 * HH)][i % (2 * HH)] = d_context[(size_t)b * KK * 2 * HH + i];
    __syncthreads();
    for (int t = w; t < TT; t += 8) {
        const float* srow = d_seq + ((size_t)b * TT + t) * (2 * HH);
        float pk[KK] = {0, 0, 0, 0, 0, 0};
        for (int d = lane; d < 2 * HH; d += 32) {
            float s = srow[d];
            #pragma unroll
            for (int k = 0; k < KK; ++k) pk[k] = fmaf(s, ctx[k][d], pk[k]);
        }
        #pragma unroll
        for (int k = 0; k < KK; ++k) {
            float v = pk[k];
            for (int off = 16; off; off >>= 1) v += __shfl_xor_sync(~0u, v, off);
            if (lane == 0) en[t][k] = v;
        }
    }
    __syncthreads();
    if (w < KK) {
        float mx = -1e30f;
        for (int t = lane; t < TT; t += 32) mx = fmaxf(mx, en[t][w]);
        for (int off = 16; off; off >>= 1) mx = fmaxf(mx, __shfl_xor_sync(~0u, mx, off));
        float sum = 0.f;
        for (int t = lane; t < TT; t += 32) { float e = __expf(en[t][w] - mx); en[t][w] = e; sum += e; }
        for (int off = 16; off; off >>= 1) sum += __shfl_xor_sync(~0u, sum, off);
        float inv = 1.f / sum;
        for (int t = lane; t < TT; t += 32) en[t][w] *= inv;
    }
    __syncthreads();
    for (int d = tid; d < 2 * HH; d += 256) {
        float acc[KK] = {0, 0, 0, 0, 0, 0};
        for (int t = 0; t < TT; ++t) {
            float s = d_seq[((size_t)b * TT + t) * (2 * HH) + d];
            #pragma unroll
            for (int k = 0; k < KK; ++k) acc[k] = fmaf(s, en[t][k], acc[k]);
        }
        #pragma unroll
        for (int k = 0; k < KK; ++k)
            d_pooled[((size_t)b * KK + k) * (2 * HH) + d] = acc[k];
    }
}

// ---------------- topic -> feats -> logits -> softmax output -----------------------------
__global__ void topic_kernel(const float* __restrict__ Wtop, const float* __restrict__ btop,
                             const float* __restrict__ Wout, const float* __restrict__ bout,
                             float* __restrict__ out) {
    int b = blockIdx.x;
    __shared__ float ps[KK * 2 * HH];
    __shared__ float feats[KK * THD];
    __shared__ float lg[CLS];
    int tid = threadIdx.x; // 128
    for (int i = tid; i < KK * 2 * HH; i += 128) ps[i] = d_pooled[(size_t)b * KK * 2 * HH + i];
    __syncthreads();
    if (tid < KK * THD) {
        int k = tid / THD, th = tid - k * THD;
        float acc = btop[tid];
        const float* wp = Wtop + (size_t)k * (2 * HH) * THD + th;
        #pragma unroll 4
        for (int d = 0; d < 2 * HH; ++d) acc += ps[k * 2 * HH + d] * wp[d * THD];
        feats[tid] = fmaxf(acc, 0.f);
    }
    __syncthreads();
    if (tid < CLS) {
        float acc = bout[tid];
        for (int e = 0; e < KK * THD; ++e) acc += feats[e] * Wout[e * CLS + tid];
        lg[tid] = acc;
    }
    __syncthreads();
    if (tid < CLS) {
        float mx = lg[0];
        #pragma unroll
        for (int c = 1; c < CLS; ++c) mx = fmaxf(mx, lg[c]);
        float sum = 0.f;
        #pragma unroll
        for (int c = 0; c < CLS; ++c) sum += __expf(lg[c] - mx);
        out[b * CLS + tid] = __expf(lg[tid] - mx) / sum;
    }
}

// ---------------- orthogonality regularizer: per-batch partial then reduce ----------------
__global__ void reg_partial_kernel() {
    int b = blockIdx.x;
    __shared__ float cs[KK * 2 * HH];
    __shared__ float D[KK * KK];
    int tid = threadIdx.x; // 256
    int w = tid >> 5, lane = tid & 31;
    for (int i = tid; i < KK * 2 * HH; i += 256) cs[i] = d_context[(size_t)b * KK * 2 * HH + i];
    __syncthreads();
    for (int p = w; p < KK * KK; p += 8) {
        int k = p / KK, j = p - k * KK;
        float v = 0.f;
        for (int d = lane; d < 2 * HH; d += 32) v += cs[k * 2 * HH + d] * cs[j * 2 * HH + d];
        for (int off = 16; off; off >>= 1) v += __shfl_xor_sync(~0u, v, off);
        if (lane == 0) D[p] = v;
    }
    __syncthreads();
    if (tid == 0) {
        float nk[KK];
        #pragma unroll
        for (int k = 0; k < KK; ++k) nk[k] = fmaxf(sqrtf(D[k * KK + k]), 1e-12f);
        float S = 0.f;
        for (int k = 0; k < KK; ++k)
            for (int j = 0; j < KK; ++j) {
                float g = D[k * KK + j] / (nk[k] * nk[j]) - (k == j ? 1.f : 0.f);
                S += g * g;
            }
        d_regpart[b] = sqrtf(S);
    }
}

__global__ void reg_final_kernel(float* __restrict__ regout) {
    __shared__ float s[BB];
    int tid = threadIdx.x; // 128
    s[tid] = d_regpart[tid];
    __syncthreads();
    for (int off = 64; off; off >>= 1) {
        if (tid < off) s[tid] += s[tid + off];
        __syncthreads();
    }
    if (tid == 0) *regout = s[0] / (float)BB;
}

// ---------------- launch ------------------------------------------------------------------
extern "C" void kernel_launch(void* const* d_in, const int* in_sizes, int n_in,
                              void* d_out, int out_size) {
    const float* x      = (const float*)d_in[0];
    const float* Wih_f  = (const float*)d_in[1];
    const float* Whh_f  = (const float*)d_in[2];
    const float* bih_f  = (const float*)d_in[3];
    const float* bhh_f  = (const float*)d_in[4];
    const float* Wih_b  = (const float*)d_in[5];
    const float* Whh_b  = (const float*)d_in[6];
    const float* bih_b  = (const float*)d_in[7];
    const float* bhh_b  = (const float*)d_in[8];
    const float* attn_c = (const float*)d_in[9];
    const float* Wattn  = (const float*)d_in[10];
    const float* battn  = (const float*)d_in[11];
    const float* Wtop   = (const float*)d_in[12];
    const float* btop   = (const float*)d_in[13];
    const float* Wout   = (const float*)d_in[14];
    const float* bout   = (const float*)d_in[15];
    float* out = (float*)d_out;

    const int scan_smem = NPAIR * WPAD * 4 + (2 * 152 + 2 * 452 + 452) * 4; // ~147 KB
    cudaFuncSetAttribute(scan_kernel, cudaFuncAttributeMaxDynamicSharedMemorySize, scan_smem);

    prep_kernel<<<(2 * NPAIR * WPAD + 255) / 256, 256>>>(Whh_f, Whh_b);
    bias2_kernel<<<KK, 320>>>(attn_c, Wattn, battn);

    gemm_gi<<<dim3(4, 512), 256>>>(x, Wih_f, bih_f, 0);
    gemm_gi<<<dim3(4, 512), 256>>>(x, Wih_b, bih_b, 1);

    scan_kernel<<<128, 256, scan_smem>>>(bhh_f, bhh_b);

    ctx_kernel<<<BB * KK, 320>>>(Wattn);
    pool_kernel<<<BB, 256>>>();
    topic_kernel<<<BB, 128>>>(Wtop, btop, Wout, bout, out);
    if (out_size > BB * CLS) {
        reg_partial_kernel<<<BB, 256>>>();
        reg_final_kernel<<<1, BB>>>(out + BB * CLS);
    }
}

// round 3
// speedup vs baseline: 3.1426x; 1.2105x over previous
#include <cuda_runtime.h>
#include <cuda_fp16.h>
#include <cstdint>

#define BB   128
#define TT   512
#define II   300
#define HH   150
#define G3   450
#define KK   6
#define CC   300
#define THD  20
#define CLS  5

#define WROW 152   // halves per weight row (150 used + 2 zero pad), 19 chunks of 8

// ---------------- scratch ----------------
__device__ float d_gi_f[(size_t)BB * TT * G3];
__device__ float d_gi_b[(size_t)BB * TT * G3];
__device__ float d_seq [(size_t)BB * TT * 2 * HH];
__device__ float d_hidden[BB * 2 * HH];
__device__ __half d_Whh_h[2][G3 * WROW];
__device__ float d_bias2[KK * 2 * HH];
__device__ float d_context[BB * KK * 2 * HH];
__device__ float d_pooled [BB * KK * 2 * HH];
__device__ float d_regpart[BB];

// ---------------- prep: Whh -> half [j][i], row padded to WROW ----------------
__global__ void prep_kernel(const float* __restrict__ Whh_f, const float* __restrict__ Whh_b) {
    int idx = blockIdx.x * blockDim.x + threadIdx.x;
    int tot = G3 * WROW;
    if (idx < 2 * tot) {
        int d = idx / tot;
        int r = idx - d * tot;
        int j = r / WROW, i = r - j * WROW;
        const float* W = d ? Whh_b : Whh_f;
        d_Whh_h[d][r] = (i < HH) ? __float2half(W[j * HH + i]) : __float2half(0.f);
    }
}

// ---------------- bias2[k][d] = battn[k][d] + sum_c attn_context[k][c]*Wattn[k][c][d] ----
__global__ void bias2_kernel(const float* __restrict__ ac, const float* __restrict__ Wattn,
                             const float* __restrict__ battn) {
    int k = blockIdx.x;
    __shared__ float as[CC];
    int tid = threadIdx.x;
    if (tid < CC) as[tid] = ac[k * CC + tid];
    __syncthreads();
    if (tid < 2 * HH) {
        float acc = battn[k * 2 * HH + tid];
        const float* w = Wattn + (size_t)k * (CC + 2 * HH) * (2 * HH) + tid;
        #pragma unroll 4
        for (int c = 0; c < CC; ++c) acc += as[c] * w[(size_t)c * (2 * HH)];
        d_bias2[k * 2 * HH + tid] = acc;
    }
}

// ---------------- gi GEMM, both directions in one launch (blockIdx.z) --------------------
// BM=128 BN=128 BK=8, 256 threads, 8x8/thread, double-buffered smem (one sync per tile).
__global__ void __launch_bounds__(256, 2)
gemm_gi(const float* __restrict__ X,
        const float* __restrict__ Wf, const float* __restrict__ Wb,
        const float* __restrict__ bf, const float* __restrict__ bb) {
    __shared__ float As[2][8][128];
    __shared__ float Bs[2][8][128];
    int which = blockIdx.z;
    const float* W    = which ? Wb : Wf;
    const float* bias = which ? bb : bf;
    float* O          = which ? d_gi_b : d_gi_f;

    int m0 = blockIdx.y * 128;
    int n0 = blockIdx.x * 128;
    int tid = threadIdx.x;
    int tx = tid & 15, ty = tid >> 4;

    float acc[8][8];
    #pragma unroll
    for (int i = 0; i < 8; ++i)
        #pragma unroll
        for (int j = 0; j < 8; ++j) acc[i][j] = 0.f;

    int lr = tid & 127;
    int kq = (tid >> 7) * 4;     // 0 or 4
    const float* Xr = X + (size_t)(m0 + lr) * II;
    int nB = n0 + lr;
    bool nok = (nB < G3);
    const float* Wr = W + (size_t)(nok ? nB : 0) * II;

    const int NT = (II + 7) / 8;   // 38

    float4 av, bv;
    {   // prologue: tile 0
        int ka = kq;
        av = *reinterpret_cast<const float4*>(Xr + ka);
        bv = nok ? *reinterpret_cast<const float4*>(Wr + ka) : make_float4(0, 0, 0, 0);
        As[0][kq + 0][lr] = av.x; As[0][kq + 1][lr] = av.y;
        As[0][kq + 2][lr] = av.z; As[0][kq + 3][lr] = av.w;
        Bs[0][kq + 0][lr] = bv.x; Bs[0][kq + 1][lr] = bv.y;
        Bs[0][kq + 2][lr] = bv.z; Bs[0][kq + 3][lr] = bv.w;
    }
    __syncthreads();

    for (int kt = 0; kt < NT; ++kt) {
        int cur = kt & 1;
        bool more = (kt + 1 < NT);
        if (more) {
            int ka = (kt + 1) * 8 + kq;
            bool ok = (ka < II);   // ka multiple of 4; valid float4 iff ka<=296
            av = ok ? *reinterpret_cast<const float4*>(Xr + ka) : make_float4(0, 0, 0, 0);
            bv = (ok && nok) ? *reinterpret_cast<const float4*>(Wr + ka) : make_float4(0, 0, 0, 0);
        }
        #pragma unroll
        for (int kk = 0; kk < 8; ++kk) {
            float a[8], b[8];
            *reinterpret_cast<float4*>(a)     = *reinterpret_cast<const float4*>(&As[cur][kk][ty * 8]);
            *reinterpret_cast<float4*>(a + 4) = *reinterpret_cast<const float4*>(&As[cur][kk][ty * 8 + 4]);
            *reinterpret_cast<float4*>(b)     = *reinterpret_cast<const float4*>(&Bs[cur][kk][tx * 8]);
            *reinterpret_cast<float4*>(b + 4) = *reinterpret_cast<const float4*>(&Bs[cur][kk][tx * 8 + 4]);
            #pragma unroll
            for (int i = 0; i < 8; ++i)
                #pragma unroll
                for (int j = 0; j < 8; ++j) acc[i][j] = fmaf(a[i], b[j], acc[i][j]);
        }
        if (more) {
            int nxt = cur ^ 1;
            As[nxt][kq + 0][lr] = av.x; As[nxt][kq + 1][lr] = av.y;
            As[nxt][kq + 2][lr] = av.z; As[nxt][kq + 3][lr] = av.w;
            Bs[nxt][kq + 0][lr] = bv.x; Bs[nxt][kq + 1][lr] = bv.y;
            Bs[nxt][kq + 2][lr] = bv.z; Bs[nxt][kq + 3][lr] = bv.w;
        }
        __syncthreads();
    }

    #pragma unroll
    for (int i = 0; i < 8; ++i) {
        int m = m0 + ty * 8 + i;
        float* Orow = O + (size_t)m * G3;
        #pragma unroll
        for (int j = 0; j < 8; j += 2) {
            int n = n0 + tx * 8 + j;
            if (n < G3) {
                float2 v = make_float2(acc[i][j] + bias[n], acc[i][j + 1] + bias[n + 1]);
                *reinterpret_cast<float2*>(Orow + n) = v;
            }
        }
    }
}

// ---------------- persistent bidirectional GRU scan (HFMA2, 512 threads) -----------------
__device__ __forceinline__ float sigm(float x) { return 1.f / (1.f + __expf(-x)); }
__device__ __forceinline__ float fast_tanh(float x) {
    float y; asm("tanh.approx.f32 %0, %1;" : "=f"(y) : "f"(x)); return y;
}

__global__ void __launch_bounds__(512, 1)
scan_kernel(const float* __restrict__ bhh_f, const float* __restrict__ bhh_b) {
    extern __shared__ char smraw[];
    __half*  Wsh = reinterpret_cast<__half*>(smraw);                        // G3*WROW halves (136800 B)
    __half2* h2s = reinterpret_cast<__half2*>(smraw + G3 * WROW * 2);       // WROW half2 (608 B)
    float*   ghb = reinterpret_cast<float*>(smraw + G3 * WROW * 2 + WROW * 4); // 2*452 floats
    float*   bsm = ghb + 2 * 452;                                           // 450 floats

    int bb  = blockIdx.x;
    int dir = bb >> 6;
    int p   = bb & 63;
    int b0  = 2 * p, b1 = b0 + 1;
    const float* gi  = dir ? d_gi_b : d_gi_f;
    const float* bhh = dir ? bhh_b : bhh_f;
    int tid = threadIdx.x;              // 512

    {   // copy weights (vectorized)
        const float4* src = reinterpret_cast<const float4*>(d_Whh_h[dir]);
        float4* dst = reinterpret_cast<float4*>(Wsh);
        const int nvec = G3 * WROW * 2 / 16;   // 8550
        for (int i = tid; i < nvec; i += 512) dst[i] = src[i];
    }
    for (int i = tid; i < WROW; i += 512) h2s[i] = __floats2half2_rn(0.f, 0.f);
    for (int i = tid; i < G3; i += 512) bsm[i] = bhh[i];
    __syncthreads();

    const int j = tid;
    const bool act = (j < G3);
    float bsj = act ? bsm[j] : 0.f;

    // gate-stage mapping: e = tid < 300 -> (row, jj)
    const int e = tid;
    const bool ge = (e < 2 * HH);
    const int row = (e < HH) ? 0 : 1;
    const int jj  = e - row * HH;

    const float4* wrow = act ? reinterpret_cast<const float4*>(Wsh + (size_t)j * WROW) : nullptr;
    const float4* h4 = reinterpret_cast<const float4*>(h2s);   // 38 float4 (4 half2 each)

    for (int s = 0; s < TT; ++s) {
        int t = dir ? (TT - 1 - s) : s;
        // prefetch gi for this step's gate stage
        float g_r = 0.f, g_z = 0.f, g_n = 0.f;
        size_t gbase = 0;
        if (ge) {
            gbase = ((size_t)(row ? b1 : b0) * TT + t) * G3 + jj;
            g_r = gi[gbase]; g_z = gi[gbase + HH]; g_n = gi[gbase + 2 * HH];
        }

        if (act) {
            float acc0 = bsj, acc1 = bsj;
            #pragma unroll
            for (int c = 0; c < 19; ++c) {
                float4 wv = wrow[c];
                float4 hva = h4[2 * c];
                float4 hvb = h4[2 * c + 1];
                const __half2* w2  = reinterpret_cast<const __half2*>(&wv);   // 4 half2
                const __half2* hha = reinterpret_cast<const __half2*>(&hva);  // i0..i3
                const __half2* hhb = reinterpret_cast<const __half2*>(&hvb);  // i4..i7
                __half2 pa = __hmul2(__low2half2 (w2[0]), hha[0]);
                __half2 pb = __hmul2(__high2half2(w2[0]), hha[1]);
                pa = __hfma2(__low2half2 (w2[1]), hha[2], pa);
                pb = __hfma2(__high2half2(w2[1]), hha[3], pb);
                pa = __hfma2(__low2half2 (w2[2]), hhb[0], pa);
                pb = __hfma2(__high2half2(w2[2]), hhb[1], pb);
                pa = __hfma2(__low2half2 (w2[3]), hhb[2], pa);
                pb = __hfma2(__high2half2(w2[3]), hhb[3], pb);
                float2 fa = __half22float2(pa);
                float2 fb = __half22float2(pb);
                acc0 += fa.x + fb.x;
                acc1 += fa.y + fb.y;
            }
            ghb[j]       = acc0;
            ghb[452 + j] = acc1;
        }
        __syncthreads();

        if (ge) {
            float hr = ghb[row * 452 + jj];
            float hz = ghb[row * 452 + HH + jj];
            float hn = ghb[row * 452 + 2 * HH + jj];
            float r = sigm(g_r + hr);
            float z = sigm(g_z + hz);
            float n = fast_tanh(g_n + r * hn);
            float hp = __half2float(reinterpret_cast<const __half*>(h2s)[jj * 2 + row]);
            float hv = (1.f - z) * n + z * hp;
            reinterpret_cast<__half*>(h2s)[jj * 2 + row] = __float2half(hv);
            d_seq[((size_t)(row ? b1 : b0) * TT + t) * (2 * HH) + dir * HH + jj] = hv;
        }
        __syncthreads();
    }
    if (ge) {
        float hv = __half2float(reinterpret_cast<const __half*>(h2s)[jj * 2 + row]);
        d_hidden[(size_t)(row ? b1 : b0) * (2 * HH) + dir * HH + jj] = hv;
    }
}

// ---------------- context[b][k][d] = tanh(bias2[k][d] + sum_h hidden[b][h]*Wattn[k][C+h][d])
__global__ void ctx_kernel(const float* __restrict__ Wattn) {
    int bk = blockIdx.x;
    int b = bk / KK, k = bk - b * KK;
    __shared__ float hs[2 * HH];
    int tid = threadIdx.x; // 320
    if (tid < 2 * HH) hs[tid] = d_hidden[b * 2 * HH + tid];
    __syncthreads();
    if (tid < 2 * HH) {
        float acc = d_bias2[k * 2 * HH + tid];
        const float* w = Wattn + ((size_t)k * (CC + 2 * HH) + CC) * (2 * HH) + tid;
        #pragma unroll 4
        for (int c = 0; c < 2 * HH; ++c) acc += hs[c] * w[(size_t)c * (2 * HH)];
        d_context[((size_t)b * KK + k) * (2 * HH) + tid] = tanhf(acc);
    }
}

// ---------------- energy -> softmax(t) -> pooled, fused per batch row --------------------
__global__ void pool_kernel() {
    int b = blockIdx.x;
    __shared__ float ctx[KK][2 * HH];
    __shared__ float en[TT][KK];
    int tid = threadIdx.x;              // 256
    int w = tid >> 5, lane = tid & 31;
    for (int i = tid; i < KK * 2 * HH; i += 256)
        ctx[i / (2 * HH)][i % (2 * HH)] = d_context[(size_t)b * KK * 2 * HH + i];
    __syncthreads();
    for (int t = w; t < TT; t += 8) {
        const float* srow = d_seq + ((size_t)b * TT + t) * (2 * HH);
        float pk[KK] = {0, 0, 0, 0, 0, 0};
        for (int d = lane; d < 2 * HH; d += 32) {
            float s = srow[d];
            #pragma unroll
            for (int k = 0; k < KK; ++k) pk[k] = fmaf(s, ctx[k][d], pk[k]);
        }
        #pragma unroll
        for (int k = 0; k < KK; ++k) {
            float v = pk[k];
            for (int off = 16; off; off >>= 1) v += __shfl_xor_sync(~0u, v, off);
            if (lane == 0) en[t][k] = v;
        }
    }
    __syncthreads();
    if (w < KK) {
        float mx = -1e30f;
        for (int t = lane; t < TT; t += 32) mx = fmaxf(mx, en[t][w]);
        for (int off = 16; off; off >>= 1) mx = fmaxf(mx, __shfl_xor_sync(~0u, mx, off));
        float sum = 0.f;
        for (int t = lane; t < TT; t += 32) { float e2 = __expf(en[t][w] - mx); en[t][w] = e2; sum += e2; }
        for (int off = 16; off; off >>= 1) sum += __shfl_xor_sync(~0u, sum, off);
        float inv = 1.f / sum;
        for (int t = lane; t < TT; t += 32) en[t][w] *= inv;
    }
    __syncthreads();
    for (int d = tid; d < 2 * HH; d += 256) {
        float acc[KK] = {0, 0, 0, 0, 0, 0};
        for (int t = 0; t < TT; ++t) {
            float s = d_seq[((size_t)b * TT + t) * (2 * HH) + d];
            #pragma unroll
            for (int k = 0; k < KK; ++k) acc[k] = fmaf(s, en[t][k], acc[k]);
        }
        #pragma unroll
        for (int k = 0; k < KK; ++k)
            d_pooled[((size_t)b * KK + k) * (2 * HH) + d] = acc[k];
    }
}

// ---------------- topic -> feats -> logits -> softmax output -----------------------------
__global__ void topic_kernel(const float* __restrict__ Wtop, const float* __restrict__ btop,
                             const float* __restrict__ Wout, const float* __restrict__ bout,
                             float* __restrict__ out) {
    int b = blockIdx.x;
    __shared__ float ps[KK * 2 * HH];
    __shared__ float feats[KK * THD];
    __shared__ float lg[CLS];
    int tid = threadIdx.x; // 128
    for (int i = tid; i < KK * 2 * HH; i += 128) ps[i] = d_pooled[(size_t)b * KK * 2 * HH + i];
    __syncthreads();
    if (tid < KK * THD) {
        int k = tid / THD, th = tid - k * THD;
        float acc = btop[tid];
        const float* wp = Wtop + (size_t)k * (2 * HH) * THD + th;
        #pragma unroll 4
        for (int d = 0; d < 2 * HH; ++d) acc += ps[k * 2 * HH + d] * wp[d * THD];
        feats[tid] = fmaxf(acc, 0.f);
    }
    __syncthreads();
    if (tid < CLS) {
        float acc = bout[tid];
        for (int e2 = 0; e2 < KK * THD; ++e2) acc += feats[e2] * Wout[e2 * CLS + tid];
        lg[tid] = acc;
    }
    __syncthreads();
    if (tid < CLS) {
        float mx = lg[0];
        #pragma unroll
        for (int c = 1; c < CLS; ++c) mx = fmaxf(mx, lg[c]);
        float sum = 0.f;
        #pragma unroll
        for (int c = 0; c < CLS; ++c) sum += __expf(lg[c] - mx);
        out[b * CLS + tid] = __expf(lg[tid] - mx) / sum;
    }
}

// ---------------- orthogonality regularizer ----------------------------------------------
__global__ void reg_partial_kernel() {
    int b = blockIdx.x;
    __shared__ float cs[KK * 2 * HH];
    __shared__ float D[KK * KK];
    int tid = threadIdx.x; // 256
    int w = tid >> 5, lane = tid & 31;
    for (int i = tid; i < KK * 2 * HH; i += 256) cs[i] = d_context[(size_t)b * KK * 2 * HH + i];
    __syncthreads();
    for (int p2 = w; p2 < KK * KK; p2 += 8) {
        int k = p2 / KK, j = p2 - k * KK;
        float v = 0.f;
        for (int d = lane; d < 2 * HH; d += 32) v += cs[k * 2 * HH + d] * cs[j * 2 * HH + d];
        for (int off = 16; off; off >>= 1) v += __shfl_xor_sync(~0u, v, off);
        if (lane == 0) D[p2] = v;
    }
    __syncthreads();
    if (tid == 0) {
        float nk[KK];
        #pragma unroll
        for (int k = 0; k < KK; ++k) nk[k] = fmaxf(sqrtf(D[k * KK + k]), 1e-12f);
        float S = 0.f;
        for (int k = 0; k < KK; ++k)
            for (int j = 0; j < KK; ++j) {
                float g = D[k * KK + j] / (nk[k] * nk[j]) - (k == j ? 1.f : 0.f);
                S += g * g;
            }
        d_regpart[b] = sqrtf(S);
    }
}

__global__ void reg_final_kernel(float* __restrict__ regout) {
    __shared__ float s[BB];
    int tid = threadIdx.x; // 128
    s[tid] = d_regpart[tid];
    __syncthreads();
    for (int off = 64; off; off >>= 1) {
        if (tid < off) s[tid] += s[tid + off];
        __syncthreads();
    }
    if (tid == 0) *regout = s[0] / (float)BB;
}

// ---------------- launch ------------------------------------------------------------------
extern "C" void kernel_launch(void* const* d_in, const int* in_sizes, int n_in,
                              void* d_out, int out_size) {
    const float* x      = (const float*)d_in[0];
    const float* Wih_f  = (const float*)d_in[1];
    const float* Whh_f  = (const float*)d_in[2];
    const float* bih_f  = (const float*)d_in[3];
    const float* bhh_f  = (const float*)d_in[4];
    const float* Wih_b  = (const float*)d_in[5];
    const float* Whh_b  = (const float*)d_in[6];
    const float* bih_b  = (const float*)d_in[7];
    const float* bhh_b  = (const float*)d_in[8];
    const float* attn_c = (const float*)d_in[9];
    const float* Wattn  = (const float*)d_in[10];
    const float* battn  = (const float*)d_in[11];
    const float* Wtop   = (const float*)d_in[12];
    const float* btop   = (const float*)d_in[13];
    const float* Wout   = (const float*)d_in[14];
    const float* bout   = (const float*)d_in[15];
    float* out = (float*)d_out;

    const int scan_smem = G3 * WROW * 2 + WROW * 4 + (2 * 452 + 452) * 4 + 64; // ~143 KB
    cudaFuncSetAttribute(scan_kernel, cudaFuncAttributeMaxDynamicSharedMemorySize, scan_smem);

    prep_kernel<<<(2 * G3 * WROW + 255) / 256, 256>>>(Whh_f, Whh_b);
    bias2_kernel<<<KK, 320>>>(attn_c, Wattn, battn);

    gemm_gi<<<dim3(4, 512, 2), 256>>>(x, Wih_f, Wih_b, bih_f, bih_b);

    scan_kernel<<<128, 512, scan_smem>>>(bhh_f, bhh_b);

    ctx_kernel<<<BB * KK, 320>>>(Wattn);
    pool_kernel<<<BB, 256>>>();
    topic_kernel<<<BB, 128>>>(Wtop, btop, Wout, bout, out);
    if (out_size > BB * CLS) {
        reg_partial_kernel<<<BB, 256>>>();
        reg_final_kernel<<<1, BB>>>(out + BB * CLS);
    }
}

// round 4
// speedup vs baseline: 4.5830x; 1.4583x over previous
#include <cuda_runtime.h>
#include <cuda_fp16.h>
#include <cstdint>

#define BB   128
#define TT   512
#define II   300
#define HH   150
#define G3   450
#define KK   6
#define CC   300
#define THD  20
#define CLS  5

#define WROW 152   // halves per weight row (150 used + 2 zero pad), 19 uint4 chunks

// ---------------- scratch ----------------
__device__ float d_gi_f[(size_t)BB * TT * G3];
__device__ float d_gi_b[(size_t)BB * TT * G3];
__device__ float d_seq [(size_t)BB * TT * 2 * HH];
__device__ float d_hidden[BB * 2 * HH];
__device__ __half d_Whh_h[2][G3 * WROW];
__device__ float d_bias2[KK * 2 * HH];
__device__ float d_context[BB * KK * 2 * HH];
__device__ float d_pooled [BB * KK * 2 * HH];
__device__ float d_regpart[BB];

// ---------------- prep: Whh -> half [j][i], row padded to WROW ----------------
__global__ void prep_kernel(const float* __restrict__ Whh_f, const float* __restrict__ Whh_b) {
    int idx = blockIdx.x * blockDim.x + threadIdx.x;
    int tot = G3 * WROW;
    if (idx < 2 * tot) {
        int d = idx / tot;
        int r = idx - d * tot;
        int j = r / WROW, i = r - j * WROW;
        const float* W = d ? Whh_b : Whh_f;
        d_Whh_h[d][r] = (i < HH) ? __float2half(W[j * HH + i]) : __float2half(0.f);
    }
}

// ---------------- bias2 ----------------
__global__ void bias2_kernel(const float* __restrict__ ac, const float* __restrict__ Wattn,
                             const float* __restrict__ battn) {
    int k = blockIdx.x;
    __shared__ float as[CC];
    int tid = threadIdx.x;
    if (tid < CC) as[tid] = ac[k * CC + tid];
    __syncthreads();
    if (tid < 2 * HH) {
        float acc = battn[k * 2 * HH + tid];
        const float* w = Wattn + (size_t)k * (CC + 2 * HH) * (2 * HH) + tid;
        #pragma unroll 4
        for (int c = 0; c < CC; ++c) acc += as[c] * w[(size_t)c * (2 * HH)];
        d_bias2[k * 2 * HH + tid] = acc;
    }
}

// ---------------- tf32 helpers ----------------
__device__ __forceinline__ uint32_t f2tf32(float f) {
    uint32_t r;
    asm("cvt.rna.tf32.f32 %0, %1;" : "=r"(r) : "f"(f));
    return r;
}

// ---------------- gi GEMM via tf32 mma.sync (tensor pipe) --------------------------------
// BM=128 BN=64 BK=16, 256 threads (8 warps: 4 along M x 2 along N).
// smem tiles stored [row][k] with stride 20 (conflict-free for frag pattern).
__global__ void __launch_bounds__(256, 2)
gemm_gi(const float* __restrict__ X,
        const float* __restrict__ Wf, const float* __restrict__ Wb,
        const float* __restrict__ bf, const float* __restrict__ bb) {
    __shared__ float As[2][128][20];
    __shared__ float Bs[2][64][20];
    int which = blockIdx.z;
    const float* W    = which ? Wb : Wf;
    const float* bias = which ? bb : bf;
    float* O          = which ? d_gi_b : d_gi_f;

    int m0 = blockIdx.y * 128;
    int n0 = blockIdx.x * 64;
    int tid = threadIdx.x;
    int wid = tid >> 5, lane = tid & 31;
    int warpM = (wid & 3) * 32;        // 2 m16 tiles
    int warpN = (wid >> 2) * 32;       // 4 n8 tiles
    int r = lane >> 2, c = lane & 3;

    float acc[2][4][4];
    #pragma unroll
    for (int mt = 0; mt < 2; ++mt)
        #pragma unroll
        for (int nt = 0; nt < 4; ++nt)
            #pragma unroll
            for (int q = 0; q < 4; ++q) acc[mt][nt][q] = 0.f;

    // global load mapping
    int am = tid >> 1, akc = (tid & 1) * 8;       // A: row am, k offset akc (2 float4)
    int bn = tid >> 2, bkc = (tid & 3) * 4;       // B: row bn, k offset bkc (1 float4)
    const float* Xr = X + (size_t)(m0 + am) * II;
    bool nok = (n0 + bn < G3);
    const float* Wr = W + (size_t)(nok ? (n0 + bn) : 0) * II;

    const int NT = (II + 15) / 16;   // 19

    float4 av0, av1, bv;
    auto ld4 = [](const float* p, bool ok) {
        return ok ? *reinterpret_cast<const float4*>(p) : make_float4(0.f, 0.f, 0.f, 0.f);
    };
    {   // prologue tile 0
        av0 = ld4(Xr + akc, akc + 3 < II);
        av1 = ld4(Xr + akc + 4, akc + 7 < II);
        bv  = ld4(Wr + bkc, nok && (bkc + 3 < II));
        float* ap = &As[0][am][akc];
        ap[0] = __uint_as_float(f2tf32(av0.x)); ap[1] = __uint_as_float(f2tf32(av0.y));
        ap[2] = __uint_as_float(f2tf32(av0.z)); ap[3] = __uint_as_float(f2tf32(av0.w));
        ap[4] = __uint_as_float(f2tf32(av1.x)); ap[5] = __uint_as_float(f2tf32(av1.y));
        ap[6] = __uint_as_float(f2tf32(av1.z)); ap[7] = __uint_as_float(f2tf32(av1.w));
        float* bp = &Bs[0][bn][bkc];
        bp[0] = __uint_as_float(f2tf32(bv.x)); bp[1] = __uint_as_float(f2tf32(bv.y));
        bp[2] = __uint_as_float(f2tf32(bv.z)); bp[3] = __uint_as_float(f2tf32(bv.w));
    }
    __syncthreads();

    for (int it = 0; it < NT; ++it) {
        int cur = it & 1;
        bool more = (it + 1 < NT);
        if (more) {
            int k0 = (it + 1) * 16;
            av0 = ld4(Xr + k0 + akc,     k0 + akc + 3 < II);
            av1 = ld4(Xr + k0 + akc + 4, k0 + akc + 7 < II);
            bv  = ld4(Wr + k0 + bkc, nok && (k0 + bkc + 3 < II));
        }
        #pragma unroll
        for (int kk = 0; kk < 16; kk += 8) {
            uint32_t a[2][4], b[4][2];
            #pragma unroll
            for (int mt = 0; mt < 2; ++mt) {
                int row = warpM + mt * 16 + r;
                a[mt][0] = __float_as_uint(As[cur][row    ][kk + c]);
                a[mt][1] = __float_as_uint(As[cur][row + 8][kk + c]);
                a[mt][2] = __float_as_uint(As[cur][row    ][kk + c + 4]);
                a[mt][3] = __float_as_uint(As[cur][row + 8][kk + c + 4]);
            }
            #pragma unroll
            for (int nt = 0; nt < 4; ++nt) {
                int col = warpN + nt * 8 + r;
                b[nt][0] = __float_as_uint(Bs[cur][col][kk + c]);
                b[nt][1] = __float_as_uint(Bs[cur][col][kk + c + 4]);
            }
            #pragma unroll
            for (int mt = 0; mt < 2; ++mt)
                #pragma unroll
                for (int nt = 0; nt < 4; ++nt) {
                    asm volatile(
                        "mma.sync.aligned.m16n8k8.row.col.f32.tf32.tf32.f32 "
                        "{%0,%1,%2,%3}, {%4,%5,%6,%7}, {%8,%9}, {%0,%1,%2,%3};"
                        : "+f"(acc[mt][nt][0]), "+f"(acc[mt][nt][1]),
                          "+f"(acc[mt][nt][2]), "+f"(acc[mt][nt][3])
                        : "r"(a[mt][0]), "r"(a[mt][1]), "r"(a[mt][2]), "r"(a[mt][3]),
                          "r"(b[nt][0]), "r"(b[nt][1]));
                }
        }
        if (more) {
            int nxt = cur ^ 1;
            float* ap = &As[nxt][am][akc];
            ap[0] = __uint_as_float(f2tf32(av0.x)); ap[1] = __uint_as_float(f2tf32(av0.y));
            ap[2] = __uint_as_float(f2tf32(av0.z)); ap[3] = __uint_as_float(f2tf32(av0.w));
            ap[4] = __uint_as_float(f2tf32(av1.x)); ap[5] = __uint_as_float(f2tf32(av1.y));
            ap[6] = __uint_as_float(f2tf32(av1.z)); ap[7] = __uint_as_float(f2tf32(av1.w));
            float* bp = &Bs[nxt][bn][bkc];
            bp[0] = __uint_as_float(f2tf32(bv.x)); bp[1] = __uint_as_float(f2tf32(bv.y));
            bp[2] = __uint_as_float(f2tf32(bv.z)); bp[3] = __uint_as_float(f2tf32(bv.w));
        }
        __syncthreads();
    }

    // epilogue: O[m][n] = acc + bias[n]
    #pragma unroll
    for (int mt = 0; mt < 2; ++mt) {
        #pragma unroll
        for (int half = 0; half < 2; ++half) {
            int m = m0 + warpM + mt * 16 + r + half * 8;
            float* Orow = O + (size_t)m * G3;
            #pragma unroll
            for (int nt = 0; nt < 4; ++nt) {
                int col = n0 + warpN + nt * 8 + 2 * c;
                if (col < G3) {
                    float v0 = acc[mt][nt][half * 2 + 0] + bias[col];
                    float v1 = acc[mt][nt][half * 2 + 1] + bias[col + 1];
                    *reinterpret_cast<float2*>(Orow + col) = make_float2(v0, v1);
                }
            }
        }
    }
}

// ---------------- persistent bidirectional GRU scan -------------------------------------
// 512 threads, 2 batch rows (half2 lanes), weights register-resident, half2 accumulation.
__device__ __forceinline__ float sigm(float x) { return 1.f / (1.f + __expf(-x)); }
__device__ __forceinline__ float fast_tanh(float x) {
    float y; asm("tanh.approx.f32 %0, %1;" : "=f"(y) : "f"(x)); return y;
}

__global__ void __launch_bounds__(512, 1)
scan_kernel(const float* __restrict__ bhh_f, const float* __restrict__ bhh_b) {
    __shared__ __align__(16) __half2 h2s[WROW];   // (h_b0[i], h_b1[i])
    __shared__ float ghb[2 * 452];
    __shared__ float bsm[G3];

    int bb  = blockIdx.x;
    int dir = bb >> 6;
    int p   = bb & 63;
    int b0  = 2 * p, b1 = b0 + 1;
    const float* gi  = dir ? d_gi_b : d_gi_f;
    const float* bhh = dir ? bhh_b : bhh_f;
    int tid = threadIdx.x;              // 512

    for (int i = tid; i < WROW; i += 512) h2s[i] = __floats2half2_rn(0.f, 0.f);
    for (int i = tid; i < G3; i += 512) bsm[i] = bhh[i];

    const int j = tid;
    const bool act = (j < G3);

    // register-resident weights: 76 half2 (one row of Whh, padded)
    __half2 wr[76];
    if (act) {
        const uint4* wrow = reinterpret_cast<const uint4*>(d_Whh_h[dir] + (size_t)j * WROW);
        #pragma unroll
        for (int cdx = 0; cdx < 19; ++cdx) {
            uint4 v = wrow[cdx];
            wr[4 * cdx + 0] = *reinterpret_cast<__half2*>(&v.x);
            wr[4 * cdx + 1] = *reinterpret_cast<__half2*>(&v.y);
            wr[4 * cdx + 2] = *reinterpret_cast<__half2*>(&v.z);
            wr[4 * cdx + 3] = *reinterpret_cast<__half2*>(&v.w);
        }
    }
    __syncthreads();
    float bsj = act ? bsm[j] : 0.f;

    // gate-stage mapping
    const int e = tid;
    const bool ge = (e < 2 * HH);
    const int row = (e < HH) ? 0 : 1;
    const int jj  = e - row * HH;

    const float4* h4 = reinterpret_cast<const float4*>(h2s);   // 38 float4

    for (int s = 0; s < TT; ++s) {
        int t = dir ? (TT - 1 - s) : s;
        float g_r = 0.f, g_z = 0.f, g_n = 0.f;
        if (ge) {
            size_t gbase = ((size_t)(row ? b1 : b0) * TT + t) * G3 + jj;
            g_r = gi[gbase]; g_z = gi[gbase + HH]; g_n = gi[gbase + 2 * HH];
        }

        if (act) {
            __half2 a0 = __floats2half2_rn(0.f, 0.f), a1 = a0, a2 = a0, a3 = a0;
            __half2 a4 = a0, a5 = a0, a6 = a0, a7 = a0;
            #pragma unroll
            for (int cdx = 0; cdx < 19; ++cdx) {
                float4 hva = h4[2 * cdx];
                float4 hvb = h4[2 * cdx + 1];
                const __half2* hha = reinterpret_cast<const __half2*>(&hva);  // i = 8c..8c+3
                const __half2* hhb = reinterpret_cast<const __half2*>(&hvb);  // i = 8c+4..8c+7
                __half2 w0 = wr[4 * cdx + 0], w1 = wr[4 * cdx + 1];
                __half2 w2 = wr[4 * cdx + 2], w3 = wr[4 * cdx + 3];
                a0 = __hfma2(__low2half2 (w0), hha[0], a0);
                a1 = __hfma2(__high2half2(w0), hha[1], a1);
                a2 = __hfma2(__low2half2 (w1), hha[2], a2);
                a3 = __hfma2(__high2half2(w1), hha[3], a3);
                a4 = __hfma2(__low2half2 (w2), hhb[0], a4);
                a5 = __hfma2(__high2half2(w2), hhb[1], a5);
                a6 = __hfma2(__low2half2 (w3), hhb[2], a6);
                a7 = __hfma2(__high2half2(w3), hhb[3], a7);
            }
            a0 = __hadd2(a0, a4); a1 = __hadd2(a1, a5);
            a2 = __hadd2(a2, a6); a3 = __hadd2(a3, a7);
            a0 = __hadd2(a0, a2); a1 = __hadd2(a1, a3);
            a0 = __hadd2(a0, a1);
            float2 f = __half22float2(a0);
            ghb[j]       = bsj + f.x;
            ghb[452 + j] = bsj + f.y;
        }
        __syncthreads();

        if (ge) {
            float hr = ghb[row * 452 + jj];
            float hz = ghb[row * 452 + HH + jj];
            float hn = ghb[row * 452 + 2 * HH + jj];
            float rg = sigm(g_r + hr);
            float zg = sigm(g_z + hz);
            float ng = fast_tanh(g_n + rg * hn);
            float hp = __half2float(reinterpret_cast<const __half*>(h2s)[jj * 2 + row]);
            float hv = (1.f - zg) * ng + zg * hp;
            reinterpret_cast<__half*>(h2s)[jj * 2 + row] = __float2half(hv);
            d_seq[((size_t)(row ? b1 : b0) * TT + t) * (2 * HH) + dir * HH + jj] = hv;
        }
        __syncthreads();
    }
    if (ge) {
        float hv = __half2float(reinterpret_cast<const __half*>(h2s)[jj * 2 + row]);
        d_hidden[(size_t)(row ? b1 : b0) * (2 * HH) + dir * HH + jj] = hv;
    }
}

// ---------------- context ----------------
__global__ void ctx_kernel(const float* __restrict__ Wattn) {
    int bk = blockIdx.x;
    int b = bk / KK, k = bk - b * KK;
    __shared__ float hs[2 * HH];
    int tid = threadIdx.x; // 320
    if (tid < 2 * HH) hs[tid] = d_hidden[b * 2 * HH + tid];
    __syncthreads();
    if (tid < 2 * HH) {
        float acc = d_bias2[k * 2 * HH + tid];
        const float* w = Wattn + ((size_t)k * (CC + 2 * HH) + CC) * (2 * HH) + tid;
        #pragma unroll 4
        for (int c = 0; c < 2 * HH; ++c) acc += hs[c] * w[(size_t)c * (2 * HH)];
        d_context[((size_t)b * KK + k) * (2 * HH) + tid] = tanhf(acc);
    }
}

// ---------------- energy -> softmax(t) -> pooled ----------------
__global__ void pool_kernel() {
    int b = blockIdx.x;
    __shared__ float ctx[KK][2 * HH];
    __shared__ float en[TT][KK];
    int tid = threadIdx.x;              // 256
    int w = tid >> 5, lane = tid & 31;
    for (int i = tid; i < KK * 2 * HH; i += 256)
        ctx[i / (2 * HH)][i % (2 * HH)] = d_context[(size_t)b * KK * 2 * HH + i];
    __syncthreads();
    for (int t = w; t < TT; t += 8) {
        const float* srow = d_seq + ((size_t)b * TT + t) * (2 * HH);
        float pk[KK] = {0, 0, 0, 0, 0, 0};
        for (int d = lane; d < 2 * HH; d += 32) {
            float s = srow[d];
            #pragma unroll
            for (int k = 0; k < KK; ++k) pk[k] = fmaf(s, ctx[k][d], pk[k]);
        }
        #pragma unroll
        for (int k = 0; k < KK; ++k) {
            float v = pk[k];
            for (int off = 16; off; off >>= 1) v += __shfl_xor_sync(~0u, v, off);
            if (lane == 0) en[t][k] = v;
        }
    }
    __syncthreads();
    if (w < KK) {
        float mx = -1e30f;
        for (int t = lane; t < TT; t += 32) mx = fmaxf(mx, en[t][w]);
        for (int off = 16; off; off >>= 1) mx = fmaxf(mx, __shfl_xor_sync(~0u, mx, off));
        float sum = 0.f;
        for (int t = lane; t < TT; t += 32) { float e2 = __expf(en[t][w] - mx); en[t][w] = e2; sum += e2; }
        for (int off = 16; off; off >>= 1) sum += __shfl_xor_sync(~0u, sum, off);
        float inv = 1.f / sum;
        for (int t = lane; t < TT; t += 32) en[t][w] *= inv;
    }
    __syncthreads();
    for (int d = tid; d < 2 * HH; d += 256) {
        float acc[KK] = {0, 0, 0, 0, 0, 0};
        for (int t = 0; t < TT; ++t) {
            float s = d_seq[((size_t)b * TT + t) * (2 * HH) + d];
            #pragma unroll
            for (int k = 0; k < KK; ++k) acc[k] = fmaf(s, en[t][k], acc[k]);
        }
        #pragma unroll
        for (int k = 0; k < KK; ++k)
            d_pooled[((size_t)b * KK + k) * (2 * HH) + d] = acc[k];
    }
}

// ---------------- topic -> logits -> softmax ----------------
__global__ void topic_kernel(const float* __restrict__ Wtop, const float* __restrict__ btop,
                             const float* __restrict__ Wout, const float* __restrict__ bout,
                             float* __restrict__ out) {
    int b = blockIdx.x;
    __shared__ float ps[KK * 2 * HH];
    __shared__ float feats[KK * THD];
    __shared__ float lg[CLS];
    int tid = threadIdx.x; // 128
    for (int i = tid; i < KK * 2 * HH; i += 128) ps[i] = d_pooled[(size_t)b * KK * 2 * HH + i];
    __syncthreads();
    if (tid < KK * THD) {
        int k = tid / THD, th = tid - k * THD;
        float acc = btop[tid];
        const float* wp = Wtop + (size_t)k * (2 * HH) * THD + th;
        #pragma unroll 4
        for (int d = 0; d < 2 * HH; ++d) acc += ps[k * 2 * HH + d] * wp[d * THD];
        feats[tid] = fmaxf(acc, 0.f);
    }
    __syncthreads();
    if (tid < CLS) {
        float acc = bout[tid];
        for (int e2 = 0; e2 < KK * THD; ++e2) acc += feats[e2] * Wout[e2 * CLS + tid];
        lg[tid] = acc;
    }
    __syncthreads();
    if (tid < CLS) {
        float mx = lg[0];
        #pragma unroll
        for (int c = 1; c < CLS; ++c) mx = fmaxf(mx, lg[c]);
        float sum = 0.f;
        #pragma unroll
        for (int c = 0; c < CLS; ++c) sum += __expf(lg[c] - mx);
        out[b * CLS + tid] = __expf(lg[tid] - mx) / sum;
    }
}

// ---------------- orthogonality regularizer ----------------
__global__ void reg_partial_kernel() {
    int b = blockIdx.x;
    __shared__ float cs[KK * 2 * HH];
    __shared__ float D[KK * KK];
    int tid = threadIdx.x; // 256
    int w = tid >> 5, lane = tid & 31;
    for (int i = tid; i < KK * 2 * HH; i += 256) cs[i] = d_context[(size_t)b * KK * 2 * HH + i];
    __syncthreads();
    for (int p2 = w; p2 < KK * KK; p2 += 8) {
        int k = p2 / KK, j = p2 - k * KK;
        float v = 0.f;
        for (int d = lane; d < 2 * HH; d += 32) v += cs[k * 2 * HH + d] * cs[j * 2 * HH + d];
        for (int off = 16; off; off >>= 1) v += __shfl_xor_sync(~0u, v, off);
        if (lane == 0) D[p2] = v;
    }
    __syncthreads();
    if (tid == 0) {
        float nk[KK];
        #pragma unroll
        for (int k = 0; k < KK; ++k) nk[k] = fmaxf(sqrtf(D[k * KK + k]), 1e-12f);
        float S = 0.f;
        for (int k = 0; k < KK; ++k)
            for (int j = 0; j < KK; ++j) {
                float g = D[k * KK + j] / (nk[k] * nk[j]) - (k == j ? 1.f : 0.f);
                S += g * g;
            }
        d_regpart[b] = sqrtf(S);
    }
}

__global__ void reg_final_kernel(float* __restrict__ regout) {
    __shared__ float s[BB];
    int tid = threadIdx.x; // 128
    s[tid] = d_regpart[tid];
    __syncthreads();
    for (int off = 64; off; off >>= 1) {
        if (tid < off) s[tid] += s[tid + off];
        __syncthreads();
    }
    if (tid == 0) *regout = s[0] / (float)BB;
}

// ---------------- launch ------------------------------------------------------------------
extern "C" void kernel_launch(void* const* d_in, const int* in_sizes, int n_in,
                              void* d_out, int out_size) {
    const float* x      = (const float*)d_in[0];
    const float* Wih_f  = (const float*)d_in[1];
    const float* Whh_f  = (const float*)d_in[2];
    const float* bih_f  = (const float*)d_in[3];
    const float* bhh_f  = (const float*)d_in[4];
    const float* Wih_b  = (const float*)d_in[5];
    const float* Whh_b  = (const float*)d_in[6];
    const float* bih_b  = (const float*)d_in[7];
    const float* bhh_b  = (const float*)d_in[8];
    const float* attn_c = (const float*)d_in[9];
    const float* Wattn  = (const float*)d_in[10];
    const float* battn  = (const float*)d_in[11];
    const float* Wtop   = (const float*)d_in[12];
    const float* btop   = (const float*)d_in[13];
    const float* Wout   = (const float*)d_in[14];
    const float* bout   = (const float*)d_in[15];
    float* out = (float*)d_out;

    prep_kernel<<<(2 * G3 * WROW + 255) / 256, 256>>>(Whh_f, Whh_b);
    bias2_kernel<<<KK, 320>>>(attn_c, Wattn, battn);

    gemm_gi<<<dim3(8, 512, 2), 256>>>(x, Wih_f, Wih_b, bih_f, bih_b);

    scan_kernel<<<128, 512>>>(bhh_f, bhh_b);

    ctx_kernel<<<BB * KK, 320>>>(Wattn);
    pool_kernel<<<BB, 256>>>();
    topic_kernel<<<BB, 128>>>(Wtop, btop, Wout, bout, out);
    if (out_size > BB * CLS) {
        reg_partial_kernel<<<BB, 256>>>();
        reg_final_kernel<<<1, BB>>>(out + BB * CLS);
    }
}

// round 5
// speedup vs baseline: 4.6651x; 1.0179x over previous
#include <cuda_runtime.h>
#include <cuda_fp16.h>
#include <cstdint>

#define BB   128
#define TT   512
#define II   300
#define HH   150
#define G3   450
#define KK   6
#define CC   300
#define THD  20
#define CLS  5

#define WROW 152   // halves per weight row (150 used + 2 zero pad), 19 uint4 chunks

// ---------------- scratch ----------------
__device__ float d_gi_f[(size_t)BB * TT * G3];
__device__ float d_gi_b[(size_t)BB * TT * G3];
__device__ float d_seq [(size_t)BB * TT * 2 * HH];
__device__ float d_hidden[BB * 2 * HH];
__device__ __half d_Whh_h[2][G3 * WROW];
__device__ float d_bias2[KK * 2 * HH];
__device__ float d_context[BB * KK * 2 * HH];
__device__ float d_pooled [BB * KK * 2 * HH];
__device__ float d_regpart[BB];

// ---------------- prep: Whh -> half [j][i], row padded to WROW ----------------
__global__ void prep_kernel(const float* __restrict__ Whh_f, const float* __restrict__ Whh_b) {
    int idx = blockIdx.x * blockDim.x + threadIdx.x;
    int tot = G3 * WROW;
    if (idx < 2 * tot) {
        int d = idx / tot;
        int r = idx - d * tot;
        int j = r / WROW, i = r - j * WROW;
        const float* W = d ? Whh_b : Whh_f;
        d_Whh_h[d][r] = (i < HH) ? __float2half(W[j * HH + i]) : __float2half(0.f);
    }
}

// ---------------- bias2 ----------------
__global__ void bias2_kernel(const float* __restrict__ ac, const float* __restrict__ Wattn,
                             const float* __restrict__ battn) {
    int k = blockIdx.x;
    __shared__ float as[CC];
    int tid = threadIdx.x;
    if (tid < CC) as[tid] = ac[k * CC + tid];
    __syncthreads();
    if (tid < 2 * HH) {
        float acc = battn[k * 2 * HH + tid];
        const float* w = Wattn + (size_t)k * (CC + 2 * HH) * (2 * HH) + tid;
        #pragma unroll 4
        for (int c = 0; c < CC; ++c) acc += as[c] * w[(size_t)c * (2 * HH)];
        d_bias2[k * 2 * HH + tid] = acc;
    }
}

// ---------------- tf32 helpers ----------------
__device__ __forceinline__ uint32_t f2tf32(float f) {
    uint32_t r;
    asm("cvt.rna.tf32.f32 %0, %1;" : "=r"(r) : "f"(f));
    return r;
}

// ---------------- gi GEMM via tf32 mma.sync (tensor pipe) --------------------------------
// BM=128 BN=64 BK=16, 256 threads (8 warps: 4 along M x 2 along N).
// smem tiles stored [row][k] with stride 20 (conflict-free for frag pattern).
__global__ void __launch_bounds__(256, 2)
gemm_gi(const float* __restrict__ X,
        const float* __restrict__ Wf, const float* __restrict__ Wb,
        const float* __restrict__ bf, const float* __restrict__ bb) {
    __shared__ float As[2][128][20];
    __shared__ float Bs[2][64][20];
    int which = blockIdx.z;
    const float* W    = which ? Wb : Wf;
    const float* bias = which ? bb : bf;
    float* O          = which ? d_gi_b : d_gi_f;

    int m0 = blockIdx.y * 128;
    int n0 = blockIdx.x * 64;
    int tid = threadIdx.x;
    int wid = tid >> 5, lane = tid & 31;
    int warpM = (wid & 3) * 32;        // 2 m16 tiles
    int warpN = (wid >> 2) * 32;       // 4 n8 tiles
    int r = lane >> 2, c = lane & 3;

    float acc[2][4][4];
    #pragma unroll
    for (int mt = 0; mt < 2; ++mt)
        #pragma unroll
        for (int nt = 0; nt < 4; ++nt)
            #pragma unroll
            for (int q = 0; q < 4; ++q) acc[mt][nt][q] = 0.f;

    // global load mapping
    int am = tid >> 1, akc = (tid & 1) * 8;       // A: row am, k offset akc (2 float4)
    int bn = tid >> 2, bkc = (tid & 3) * 4;       // B: row bn, k offset bkc (1 float4)
    const float* Xr = X + (size_t)(m0 + am) * II;
    bool nok = (n0 + bn < G3);
    const float* Wr = W + (size_t)(nok ? (n0 + bn) : 0) * II;

    const int NT = (II + 15) / 16;   // 19

    float4 av0, av1, bv;
    auto ld4 = [](const float* p, bool ok) {
        return ok ? *reinterpret_cast<const float4*>(p) : make_float4(0.f, 0.f, 0.f, 0.f);
    };
    {   // prologue tile 0
        av0 = ld4(Xr + akc, akc + 3 < II);
        av1 = ld4(Xr + akc + 4, akc + 7 < II);
        bv  = ld4(Wr + bkc, nok && (bkc + 3 < II));
        float* ap = &As[0][am][akc];
        ap[0] = __uint_as_float(f2tf32(av0.x)); ap[1] = __uint_as_float(f2tf32(av0.y));
        ap[2] = __uint_as_float(f2tf32(av0.z)); ap[3] = __uint_as_float(f2tf32(av0.w));
        ap[4] = __uint_as_float(f2tf32(av1.x)); ap[5] = __uint_as_float(f2tf32(av1.y));
        ap[6] = __uint_as_float(f2tf32(av1.z)); ap[7] = __uint_as_float(f2tf32(av1.w));
        float* bp = &Bs[0][bn][bkc];
        bp[0] = __uint_as_float(f2tf32(bv.x)); bp[1] = __uint_as_float(f2tf32(bv.y));
        bp[2] = __uint_as_float(f2tf32(bv.z)); bp[3] = __uint_as_float(f2tf32(bv.w));
    }
    __syncthreads();

    for (int it = 0; it < NT; ++it) {
        int cur = it & 1;
        bool more = (it + 1 < NT);
        if (more) {
            int k0 = (it + 1) * 16;
            av0 = ld4(Xr + k0 + akc,     k0 + akc + 3 < II);
            av1 = ld4(Xr + k0 + akc + 4, k0 + akc + 7 < II);
            bv  = ld4(Wr + k0 + bkc, nok && (k0 + bkc + 3 < II));
        }
        #pragma unroll
        for (int kk = 0; kk < 16; kk += 8) {
            uint32_t a[2][4], b[4][2];
            #pragma unroll
            for (int mt = 0; mt < 2; ++mt) {
                int row = warpM + mt * 16 + r;
                a[mt][0] = __float_as_uint(As[cur][row    ][kk + c]);
                a[mt][1] = __float_as_uint(As[cur][row + 8][kk + c]);
                a[mt][2] = __float_as_uint(As[cur][row    ][kk + c + 4]);
                a[mt][3] = __float_as_uint(As[cur][row + 8][kk + c + 4]);
            }
            #pragma unroll
            for (int nt = 0; nt < 4; ++nt) {
                int col = warpN + nt * 8 + r;
                b[nt][0] = __float_as_uint(Bs[cur][col][kk + c]);
                b[nt][1] = __float_as_uint(Bs[cur][col][kk + c + 4]);
            }
            #pragma unroll
            for (int mt = 0; mt < 2; ++mt)
                #pragma unroll
                for (int nt = 0; nt < 4; ++nt) {
                    asm volatile(
                        "mma.sync.aligned.m16n8k8.row.col.f32.tf32.tf32.f32 "
                        "{%0,%1,%2,%3}, {%4,%5,%6,%7}, {%8,%9}, {%0,%1,%2,%3};"
                        : "+f"(acc[mt][nt][0]), "+f"(acc[mt][nt][1]),
                          "+f"(acc[mt][nt][2]), "+f"(acc[mt][nt][3])
                        : "r"(a[mt][0]), "r"(a[mt][1]), "r"(a[mt][2]), "r"(a[mt][3]),
                          "r"(b[nt][0]), "r"(b[nt][1]));
                }
        }
        if (more) {
            int nxt = cur ^ 1;
            float* ap = &As[nxt][am][akc];
            ap[0] = __uint_as_float(f2tf32(av0.x)); ap[1] = __uint_as_float(f2tf32(av0.y));
            ap[2] = __uint_as_float(f2tf32(av0.z)); ap[3] = __uint_as_float(f2tf32(av0.w));
            ap[4] = __uint_as_float(f2tf32(av1.x)); ap[5] = __uint_as_float(f2tf32(av1.y));
            ap[6] = __uint_as_float(f2tf32(av1.z)); ap[7] = __uint_as_float(f2tf32(av1.w));
            float* bp = &Bs[nxt][bn][bkc];
            bp[0] = __uint_as_float(f2tf32(bv.x)); bp[1] = __uint_as_float(f2tf32(bv.y));
            bp[2] = __uint_as_float(f2tf32(bv.z)); bp[3] = __uint_as_float(f2tf32(bv.w));
        }
        __syncthreads();
    }

    // epilogue: O[m][n] = acc + bias[n]
    #pragma unroll
    for (int mt = 0; mt < 2; ++mt) {
        #pragma unroll
        for (int half = 0; half < 2; ++half) {
            int m = m0 + warpM + mt * 16 + r + half * 8;
            float* Orow = O + (size_t)m * G3;
            #pragma unroll
            for (int nt = 0; nt < 4; ++nt) {
                int col = n0 + warpN + nt * 8 + 2 * c;
                if (col < G3) {
                    float v0 = acc[mt][nt][half * 2 + 0] + bias[col];
                    float v1 = acc[mt][nt][half * 2 + 1] + bias[col + 1];
                    *reinterpret_cast<float2*>(Orow + col) = make_float2(v0, v1);
                }
            }
        }
    }
}

// ---------------- persistent bidirectional GRU scan -------------------------------------
// 512 threads, 2 batch rows (half2 lanes), weights register-resident, half2 accumulation.
__device__ __forceinline__ float sigm(float x) { return 1.f / (1.f + __expf(-x)); }
__device__ __forceinline__ float fast_tanh(float x) {
    float y; asm("tanh.approx.f32 %0, %1;" : "=f"(y) : "f"(x)); return y;
}

__global__ void __launch_bounds__(512, 1)
scan_kernel(const float* __restrict__ bhh_f, const float* __restrict__ bhh_b) {
    __shared__ __align__(16) __half2 h2s[WROW];   // (h_b0[i], h_b1[i])
    __shared__ float ghb[2 * 452];
    __shared__ float bsm[G3];

    int bb  = blockIdx.x;
    int dir = bb >> 6;
    int p   = bb & 63;
    int b0  = 2 * p, b1 = b0 + 1;
    const float* gi  = dir ? d_gi_b : d_gi_f;
    const float* bhh = dir ? bhh_b : bhh_f;
    int tid = threadIdx.x;              // 512

    for (int i = tid; i < WROW; i += 512) h2s[i] = __floats2half2_rn(0.f, 0.f);
    for (int i = tid; i < G3; i += 512) bsm[i] = bhh[i];

    const int j = tid;
    const bool act = (j < G3);

    // register-resident weights: 76 half2 (one row of Whh, padded)
    __half2 wr[76];
    if (act) {
        const uint4* wrow = reinterpret_cast<const uint4*>(d_Whh_h[dir] + (size_t)j * WROW);
        #pragma unroll
        for (int cdx = 0; cdx < 19; ++cdx) {
            uint4 v = wrow[cdx];
            wr[4 * cdx + 0] = *reinterpret_cast<__half2*>(&v.x);
            wr[4 * cdx + 1] = *reinterpret_cast<__half2*>(&v.y);
            wr[4 * cdx + 2] = *reinterpret_cast<__half2*>(&v.z);
            wr[4 * cdx + 3] = *reinterpret_cast<__half2*>(&v.w);
        }
    }
    __syncthreads();
    float bsj = act ? bsm[j] : 0.f;

    // gate-stage mapping
    const int e = tid;
    const bool ge = (e < 2 * HH);
    const int row = (e < HH) ? 0 : 1;
    const int jj  = e - row * HH;

    const float4* h4 = reinterpret_cast<const float4*>(h2s);   // 38 float4

    for (int s = 0; s < TT; ++s) {
        int t = dir ? (TT - 1 - s) : s;
        float g_r = 0.f, g_z = 0.f, g_n = 0.f;
        if (ge) {
            size_t gbase = ((size_t)(row ? b1 : b0) * TT + t) * G3 + jj;
            g_r = gi[gbase]; g_z = gi[gbase + HH]; g_n = gi[gbase + 2 * HH];
        }

        if (act) {
            __half2 a0 = __floats2half2_rn(0.f, 0.f), a1 = a0, a2 = a0, a3 = a0;
            __half2 a4 = a0, a5 = a0, a6 = a0, a7 = a0;
            #pragma unroll
            for (int cdx = 0; cdx < 19; ++cdx) {
                float4 hva = h4[2 * cdx];
                float4 hvb = h4[2 * cdx + 1];
                const __half2* hha = reinterpret_cast<const __half2*>(&hva);  // i = 8c..8c+3
                const __half2* hhb = reinterpret_cast<const __half2*>(&hvb);  // i = 8c+4..8c+7
                __half2 w0 = wr[4 * cdx + 0], w1 = wr[4 * cdx + 1];
                __half2 w2 = wr[4 * cdx + 2], w3 = wr[4 * cdx + 3];
                a0 = __hfma2(__low2half2 (w0), hha[0], a0);
                a1 = __hfma2(__high2half2(w0), hha[1], a1);
                a2 = __hfma2(__low2half2 (w1), hha[2], a2);
                a3 = __hfma2(__high2half2(w1), hha[3], a3);
                a4 = __hfma2(__low2half2 (w2), hhb[0], a4);
                a5 = __hfma2(__high2half2(w2), hhb[1], a5);
                a6 = __hfma2(__low2half2 (w3), hhb[2], a6);
                a7 = __hfma2(__high2half2(w3), hhb[3], a7);
            }
            a0 = __hadd2(a0, a4); a1 = __hadd2(a1, a5);
            a2 = __hadd2(a2, a6); a3 = __hadd2(a3, a7);
            a0 = __hadd2(a0, a2); a1 = __hadd2(a1, a3);
            a0 = __hadd2(a0, a1);
            float2 f = __half22float2(a0);
            ghb[j]       = bsj + f.x;
            ghb[452 + j] = bsj + f.y;
        }
        __syncthreads();

        if (ge) {
            float hr = ghb[row * 452 + jj];
            float hz = ghb[row * 452 + HH + jj];
            float hn = ghb[row * 452 + 2 * HH + jj];
            float rg = sigm(g_r + hr);
            float zg = sigm(g_z + hz);
            float ng = fast_tanh(g_n + rg * hn);
            float hp = __half2float(reinterpret_cast<const __half*>(h2s)[jj * 2 + row]);
            float hv = (1.f - zg) * ng + zg * hp;
            reinterpret_cast<__half*>(h2s)[jj * 2 + row] = __float2half(hv);
            d_seq[((size_t)(row ? b1 : b0) * TT + t) * (2 * HH) + dir * HH + jj] = hv;
        }
        __syncthreads();
    }
    if (ge) {
        float hv = __half2float(reinterpret_cast<const __half*>(h2s)[jj * 2 + row]);
        d_hidden[(size_t)(row ? b1 : b0) * (2 * HH) + dir * HH + jj] = hv;
    }
}

// ---------------- context ----------------
__global__ void ctx_kernel(const float* __restrict__ Wattn) {
    int bk = blockIdx.x;
    int b = bk / KK, k = bk - b * KK;
    __shared__ float hs[2 * HH];
    int tid = threadIdx.x; // 320
    if (tid < 2 * HH) hs[tid] = d_hidden[b * 2 * HH + tid];
    __syncthreads();
    if (tid < 2 * HH) {
        float acc = d_bias2[k * 2 * HH + tid];
        const float* w = Wattn + ((size_t)k * (CC + 2 * HH) + CC) * (2 * HH) + tid;
        #pragma unroll 4
        for (int c = 0; c < 2 * HH; ++c) acc += hs[c] * w[(size_t)c * (2 * HH)];
        d_context[((size_t)b * KK + k) * (2 * HH) + tid] = tanhf(acc);
    }
}

// ---------------- energy -> softmax(t) -> pooled ----------------
__global__ void pool_kernel() {
    int b = blockIdx.x;
    __shared__ float ctx[KK][2 * HH];
    __shared__ float en[TT][KK];
    int tid = threadIdx.x;              // 256
    int w = tid >> 5, lane = tid & 31;
    for (int i = tid; i < KK * 2 * HH; i += 256)
        ctx[i / (2 * HH)][i % (2 * HH)] = d_context[(size_t)b * KK * 2 * HH + i];
    __syncthreads();
    for (int t = w; t < TT; t += 8) {
        const float* srow = d_seq + ((size_t)b * TT + t) * (2 * HH);
        float pk[KK] = {0, 0, 0, 0, 0, 0};
        for (int d = lane; d < 2 * HH; d += 32) {
            float s = srow[d];
            #pragma unroll
            for (int k = 0; k < KK; ++k) pk[k] = fmaf(s, ctx[k][d], pk[k]);
        }
        #pragma unroll
        for (int k = 0; k < KK; ++k) {
            float v = pk[k];
            for (int off = 16; off; off >>= 1) v += __shfl_xor_sync(~0u, v, off);
            if (lane == 0) en[t][k] = v;
        }
    }
    __syncthreads();
    if (w < KK) {
        float mx = -1e30f;
        for (int t = lane; t < TT; t += 32) mx = fmaxf(mx, en[t][w]);
        for (int off = 16; off; off >>= 1) mx = fmaxf(mx, __shfl_xor_sync(~0u, mx, off));
        float sum = 0.f;
        for (int t = lane; t < TT; t += 32) { float e2 = __expf(en[t][w] - mx); en[t][w] = e2; sum += e2; }
        for (int off = 16; off; off >>= 1) sum += __shfl_xor_sync(~0u, sum, off);
        float inv = 1.f / sum;
        for (int t = lane; t < TT; t += 32) en[t][w] *= inv;
    }
    __syncthreads();
    for (int d = tid; d < 2 * HH; d += 256) {
        float acc[KK] = {0, 0, 0, 0, 0, 0};
        for (int t = 0; t < TT; ++t) {
            float s = d_seq[((size_t)b * TT + t) * (2 * HH) + d];
            #pragma unroll
            for (int k = 0; k < KK; ++k) acc[k] = fmaf(s, en[t][k], acc[k]);
        }
        #pragma unroll
        for (int k = 0; k < KK; ++k)
            d_pooled[((size_t)b * KK + k) * (2 * HH) + d] = acc[k];
    }
}

// ---------------- topic -> logits -> softmax ----------------
__global__ void topic_kernel(const float* __restrict__ Wtop, const float* __restrict__ btop,
                             const float* __restrict__ Wout, const float* __restrict__ bout,
                             float* __restrict__ out) {
    int b = blockIdx.x;
    __shared__ float ps[KK * 2 * HH];
    __shared__ float feats[KK * THD];
    __shared__ float lg[CLS];
    int tid = threadIdx.x; // 128
    for (int i = tid; i < KK * 2 * HH; i += 128) ps[i] = d_pooled[(size_t)b * KK * 2 * HH + i];
    __syncthreads();
    if (tid < KK * THD) {
        int k = tid / THD, th = tid - k * THD;
        float acc = btop[tid];
        const float* wp = Wtop + (size_t)k * (2 * HH) * THD + th;
        #pragma unroll 4
        for (int d = 0; d < 2 * HH; ++d) acc += ps[k * 2 * HH + d] * wp[d * THD];
        feats[tid] = fmaxf(acc, 0.f);
    }
    __syncthreads();
    if (tid < CLS) {
        float acc = bout[tid];
        for (int e2 = 0; e2 < KK * THD; ++e2) acc += feats[e2] * Wout[e2 * CLS + tid];
        lg[tid] = acc;
    }
    __syncthreads();
    if (tid < CLS) {
        float mx = lg[0];
        #pragma unroll
        for (int c = 1; c < CLS; ++c) mx = fmaxf(mx, lg[c]);
        float sum = 0.f;
        #pragma unroll
        for (int c = 0; c < CLS; ++c) sum += __expf(lg[c] - mx);
        out[b * CLS + tid] = __expf(lg[tid] - mx) / sum;
    }
}

// ---------------- orthogonality regularizer ----------------
__global__ void reg_partial_kernel() {
    int b = blockIdx.x;
    __shared__ float cs[KK * 2 * HH];
    __shared__ float D[KK * KK];
    int tid = threadIdx.x; // 256
    int w = tid >> 5, lane = tid & 31;
    for (int i = tid; i < KK * 2 * HH; i += 256) cs[i] = d_context[(size_t)b * KK * 2 * HH + i];
    __syncthreads();
    for (int p2 = w; p2 < KK * KK; p2 += 8) {
        int k = p2 / KK, j = p2 - k * KK;
        float v = 0.f;
        for (int d = lane; d < 2 * HH; d += 32) v += cs[k * 2 * HH + d] * cs[j * 2 * HH + d];
        for (int off = 16; off; off >>= 1) v += __shfl_xor_sync(~0u, v, off);
        if (lane == 0) D[p2] = v;
    }
    __syncthreads();
    if (tid == 0) {
        float nk[KK];
        #pragma unroll
        for (int k = 0; k < KK; ++k) nk[k] = fmaxf(sqrtf(D[k * KK + k]), 1e-12f);
        float S = 0.f;
        for (int k = 0; k < KK; ++k)
            for (int j = 0; j < KK; ++j) {
                float g = D[k * KK + j] / (nk[k] * nk[j]) - (k == j ? 1.f : 0.f);
                S += g * g;
            }
        d_regpart[b] = sqrtf(S);
    }
}

__global__ void reg_final_kernel(float* __restrict__ regout) {
    __shared__ float s[BB];
    int tid = threadIdx.x; // 128
    s[tid] = d_regpart[tid];
    __syncthreads();
    for (int off = 64; off; off >>= 1) {
        if (tid < off) s[tid] += s[tid + off];
        __syncthreads();
    }
    if (tid == 0) *regout = s[0] / (float)BB;
}

// ---------------- launch ------------------------------------------------------------------
extern "C" void kernel_launch(void* const* d_in, const int* in_sizes, int n_in,
                              void* d_out, int out_size) {
    const float* x      = (const float*)d_in[0];
    const float* Wih_f  = (const float*)d_in[1];
    const float* Whh_f  = (const float*)d_in[2];
    const float* bih_f  = (const float*)d_in[3];
    const float* bhh_f  = (const float*)d_in[4];
    const float* Wih_b  = (const float*)d_in[5];
    const float* Whh_b  = (const float*)d_in[6];
    const float* bih_b  = (const float*)d_in[7];
    const float* bhh_b  = (const float*)d_in[8];
    const float* attn_c = (const float*)d_in[9];
    const float* Wattn  = (const float*)d_in[10];
    const float* battn  = (const float*)d_in[11];
    const float* Wtop   = (const float*)d_in[12];
    const float* btop   = (const float*)d_in[13];
    const float* Wout   = (const float*)d_in[14];
    const float* bout   = (const float*)d_in[15];
    float* out = (float*)d_out;

    prep_kernel<<<(2 * G3 * WROW + 255) / 256, 256>>>(Whh_f, Whh_b);
    bias2_kernel<<<KK, 320>>>(attn_c, Wattn, battn);

    gemm_gi<<<dim3(8, 512, 2), 256>>>(x, Wih_f, Wih_b, bih_f, bih_b);

    scan_kernel<<<128, 512>>>(bhh_f, bhh_b);

    ctx_kernel<<<BB * KK, 320>>>(Wattn);
    pool_kernel<<<BB, 256>>>();
    topic_kernel<<<BB, 128>>>(Wtop, btop, Wout, bout, out);
    if (out_size > BB * CLS) {
        reg_partial_kernel<<<BB, 256>>>();
        reg_final_kernel<<<1, BB>>>(out + BB * CLS);
    }
}

// round 6
// speedup vs baseline: 4.9255x; 1.0558x over previous
#include <cuda_runtime.h>
#include <cuda_fp16.h>
#include <cstdint>

#define BB   128
#define TT   512
#define II   300
#define HH   150
#define G3   450
#define KK   6
#define CC   300
#define THD  20
#define CLS  5

#define WROW 152
#define APAD 40

// ---------------- scratch ----------------
__device__ float d_gi_f[(size_t)BB * TT * G3];
__device__ float d_gi_b[(size_t)BB * TT * G3];
__device__ float d_seq [(size_t)BB * TT * 2 * HH];
__device__ float d_hidden[BB * 2 * HH];
__device__ __half d_Whh_h[2][G3 * WROW];
__device__ float d_bias2[KK * 2 * HH];
__device__ float d_context[BB * KK * 2 * HH];
__device__ float d_pooled [BB * KK * 2 * HH];
__device__ float d_regpart[BB];

// ---------------- prep ----------------
__global__ void prep_kernel(const float* __restrict__ Whh_f, const float* __restrict__ Whh_b) {
    int idx = blockIdx.x * blockDim.x + threadIdx.x;
    int tot = G3 * WROW;
    if (idx < 2 * tot) {
        int d = idx / tot;
        int r = idx - d * tot;
        int j = r / WROW, i = r - j * WROW;
        const float* W = d ? Whh_b : Whh_f;
        d_Whh_h[d][r] = (i < HH) ? __float2half(W[j * HH + i]) : __float2half(0.f);
    }
}

// ---------------- bias2 ----------------
__global__ void bias2_kernel(const float* __restrict__ ac, const float* __restrict__ Wattn,
                             const float* __restrict__ battn) {
    int k = blockIdx.x;
    __shared__ float as[CC];
    int tid = threadIdx.x;
    if (tid < CC) as[tid] = ac[k * CC + tid];
    __syncthreads();
    if (tid < 2 * HH) {
        float acc = battn[k * 2 * HH + tid];
        const float* w = Wattn + (size_t)k * (CC + 2 * HH) * (2 * HH) + tid;
        #pragma unroll 4
        for (int c = 0; c < CC; ++c) acc += as[c] * w[(size_t)c * (2 * HH)];
        d_bias2[k * 2 * HH + tid] = acc;
    }
}

// ---------------- fp16 pack helper ----------------
__device__ __forceinline__ uint4 pack8h(float4 u, float4 v) {
    __half2 h0 = __floats2half2_rn(u.x, u.y);
    __half2 h1 = __floats2half2_rn(u.z, u.w);
    __half2 h2 = __floats2half2_rn(v.x, v.y);
    __half2 h3 = __floats2half2_rn(v.z, v.w);
    uint4 o;
    o.x = *reinterpret_cast<uint32_t*>(&h0);
    o.y = *reinterpret_cast<uint32_t*>(&h1);
    o.z = *reinterpret_cast<uint32_t*>(&h2);
    o.w = *reinterpret_cast<uint32_t*>(&h3);
    return o;
}

// ---------------- gi GEMM: fp16 mma.sync m16n8k16, fp32 accum ---------------------------
// BM=128 BN=64 BK=32, 256 threads (8 warps: 4 M x 2 N), double-buffered smem.
__global__ void __launch_bounds__(256, 2)
gemm_gi(const float* __restrict__ X,
        const float* __restrict__ Wf, const float* __restrict__ Wb,
        const float* __restrict__ bf, const float* __restrict__ bb) {
    __shared__ __align__(16) __half Asm[2][128 * APAD];
    __shared__ __align__(16) __half Bsm[2][64 * APAD];
    int which = blockIdx.z;
    const float* W    = which ? Wb : Wf;
    const float* bias = which ? bb : bf;
    float* O          = which ? d_gi_b : d_gi_f;

    int m0 = blockIdx.y * 128;
    int n0 = blockIdx.x * 64;
    int tid = threadIdx.x;
    int wid = tid >> 5, lane = tid & 31;
    int warpM = (wid & 3) * 32;
    int warpN = (wid >> 2) * 32;
    int gr = lane >> 2, t4 = lane & 3;

    float acc[2][4][4];
    #pragma unroll
    for (int mt = 0; mt < 2; ++mt)
        #pragma unroll
        for (int nt = 0; nt < 4; ++nt)
            #pragma unroll
            for (int q = 0; q < 4; ++q) acc[mt][nt][q] = 0.f;

    int arow = tid & 127, ash = tid >> 7;
    int bn = tid & 63, bseg = tid >> 6;
    const float* Xr = X + (size_t)(m0 + arow) * II;
    bool nok = (n0 + bn < G3);
    const float* Wr = W + (size_t)(nok ? (n0 + bn) : 0) * II;

    const int NT = (II + 31) / 32;   // 10

    auto ld4 = [](const float* p, bool ok) {
        return ok ? *reinterpret_cast<const float4*>(p) : make_float4(0.f, 0.f, 0.f, 0.f);
    };

    float4 av[4], bv[2];
    auto fetch = [&](int k0) {
        int ka = k0 + ash * 16;
        av[0] = ld4(Xr + ka,      ka +  3 < II);
        av[1] = ld4(Xr + ka + 4,  ka +  7 < II);
        av[2] = ld4(Xr + ka + 8,  ka + 11 < II);
        av[3] = ld4(Xr + ka + 12, ka + 15 < II);
        int kb = k0 + bseg * 8;
        bv[0] = ld4(Wr + kb,     nok && (kb + 3 < II));
        bv[1] = ld4(Wr + kb + 4, nok && (kb + 7 < II));
    };
    auto stage = [&](int buf) {
        uint4* ap = reinterpret_cast<uint4*>(&Asm[buf][arow * APAD + ash * 16]);
        ap[0] = pack8h(av[0], av[1]);
        ap[1] = pack8h(av[2], av[3]);
        uint4* bp = reinterpret_cast<uint4*>(&Bsm[buf][bn * APAD + bseg * 8]);
        bp[0] = pack8h(bv[0], bv[1]);
    };

    fetch(0);
    stage(0);
    __syncthreads();

    for (int it = 0; it < NT; ++it) {
        int cur = it & 1;
        bool more = (it + 1 < NT);
        if (more) fetch((it + 1) * 32);
        #pragma unroll
        for (int kk = 0; kk < 32; kk += 16) {
            uint32_t a[2][4], b[4][2];
            #pragma unroll
            for (int mt = 0; mt < 2; ++mt) {
                int row = (warpM + mt * 16 + gr) * APAD + kk + 2 * t4;
                a[mt][0] = *reinterpret_cast<const uint32_t*>(&Asm[cur][row]);
                a[mt][1] = *reinterpret_cast<const uint32_t*>(&Asm[cur][row + 8 * APAD]);
                a[mt][2] = *reinterpret_cast<const uint32_t*>(&Asm[cur][row + 8]);
                a[mt][3] = *reinterpret_cast<const uint32_t*>(&Asm[cur][row + 8 * APAD + 8]);
            }
            #pragma unroll
            for (int nt = 0; nt < 4; ++nt) {
                int col = (warpN + nt * 8 + gr) * APAD + kk + 2 * t4;
                b[nt][0] = *reinterpret_cast<const uint32_t*>(&Bsm[cur][col]);
                b[nt][1] = *reinterpret_cast<const uint32_t*>(&Bsm[cur][col + 8]);
            }
            #pragma unroll
            for (int mt = 0; mt < 2; ++mt)
                #pragma unroll
                for (int nt = 0; nt < 4; ++nt) {
                    asm volatile(
                        "mma.sync.aligned.m16n8k16.row.col.f32.f16.f16.f32 "
                        "{%0,%1,%2,%3}, {%4,%5,%6,%7}, {%8,%9}, {%0,%1,%2,%3};"
                        : "+f"(acc[mt][nt][0]), "+f"(acc[mt][nt][1]),
                          "+f"(acc[mt][nt][2]), "+f"(acc[mt][nt][3])
                        : "r"(a[mt][0]), "r"(a[mt][1]), "r"(a[mt][2]), "r"(a[mt][3]),
                          "r"(b[nt][0]), "r"(b[nt][1]));
                }
        }
        if (more) stage(cur ^ 1);
        __syncthreads();
    }

    #pragma unroll
    for (int mt = 0; mt < 2; ++mt) {
        #pragma unroll
        for (int hf = 0; hf < 2; ++hf) {
            int m = m0 + warpM + mt * 16 + gr + hf * 8;
            float* Orow = O + (size_t)m * G3;
            #pragma unroll
            for (int nt = 0; nt < 4; ++nt) {
                int col = n0 + warpN + nt * 8 + 2 * t4;
                if (col < G3) {
                    float v0 = acc[mt][nt][hf * 2 + 0] + bias[col];
                    float v1 = acc[mt][nt][hf * 2 + 1] + bias[col + 1];
                    *reinterpret_cast<float2*>(Orow + col) = make_float2(v0, v1);
                }
            }
        }
    }
}

// ---------------- persistent bidirectional GRU scan (unchanged) --------------------------
__device__ __forceinline__ float sigm(float x) { return 1.f / (1.f + __expf(-x)); }
__device__ __forceinline__ float fast_tanh(float x) {
    float y; asm("tanh.approx.f32 %0, %1;" : "=f"(y) : "f"(x)); return y;
}

__global__ void __launch_bounds__(512, 1)
scan_kernel(const float* __restrict__ bhh_f, const float* __restrict__ bhh_b) {
    __shared__ __align__(16) __half2 h2s[WROW];
    __shared__ float ghb[2 * 452];
    __shared__ float bsm[G3];

    int bb  = blockIdx.x;
    int dir = bb >> 6;
    int p   = bb & 63;
    int b0  = 2 * p, b1 = b0 + 1;
    const float* gi  = dir ? d_gi_b : d_gi_f;
    const float* bhh = dir ? bhh_b : bhh_f;
    int tid = threadIdx.x;

    for (int i = tid; i < WROW; i += 512) h2s[i] = __floats2half2_rn(0.f, 0.f);
    for (int i = tid; i < G3; i += 512) bsm[i] = bhh[i];

    const int j = tid;
    const bool act = (j < G3);

    __half2 wr[76];
    if (act) {
        const uint4* wrow = reinterpret_cast<const uint4*>(d_Whh_h[dir] + (size_t)j * WROW);
        #pragma unroll
        for (int cdx = 0; cdx < 19; ++cdx) {
            uint4 v = wrow[cdx];
            wr[4 * cdx + 0] = *reinterpret_cast<__half2*>(&v.x);
            wr[4 * cdx + 1] = *reinterpret_cast<__half2*>(&v.y);
            wr[4 * cdx + 2] = *reinterpret_cast<__half2*>(&v.z);
            wr[4 * cdx + 3] = *reinterpret_cast<__half2*>(&v.w);
        }
    }
    __syncthreads();
    float bsj = act ? bsm[j] : 0.f;

    const int e = tid;
    const bool ge = (e < 2 * HH);
    const int row = (e < HH) ? 0 : 1;
    const int jj  = e - row * HH;

    const float4* h4 = reinterpret_cast<const float4*>(h2s);

    for (int s = 0; s < TT; ++s) {
        int t = dir ? (TT - 1 - s) : s;
        float g_r = 0.f, g_z = 0.f, g_n = 0.f;
        if (ge) {
            size_t gbase = ((size_t)(row ? b1 : b0) * TT + t) * G3 + jj;
            g_r = gi[gbase]; g_z = gi[gbase + HH]; g_n = gi[gbase + 2 * HH];
        }

        if (act) {
            __half2 a0 = __floats2half2_rn(0.f, 0.f), a1 = a0, a2 = a0, a3 = a0;
            __half2 a4 = a0, a5 = a0, a6 = a0, a7 = a0;
            #pragma unroll
            for (int cdx = 0; cdx < 19; ++cdx) {
                float4 hva = h4[2 * cdx];
                float4 hvb = h4[2 * cdx + 1];
                const __half2* hha = reinterpret_cast<const __half2*>(&hva);
                const __half2* hhb = reinterpret_cast<const __half2*>(&hvb);
                __half2 w0 = wr[4 * cdx + 0], w1 = wr[4 * cdx + 1];
                __half2 w2 = wr[4 * cdx + 2], w3 = wr[4 * cdx + 3];
                a0 = __hfma2(__low2half2 (w0), hha[0], a0);
                a1 = __hfma2(__high2half2(w0), hha[1], a1);
                a2 = __hfma2(__low2half2 (w1), hha[2], a2);
                a3 = __hfma2(__high2half2(w1), hha[3], a3);
                a4 = __hfma2(__low2half2 (w2), hhb[0], a4);
                a5 = __hfma2(__high2half2(w2), hhb[1], a5);
                a6 = __hfma2(__low2half2 (w3), hhb[2], a6);
                a7 = __hfma2(__high2half2(w3), hhb[3], a7);
            }
            a0 = __hadd2(a0, a4); a1 = __hadd2(a1, a5);
            a2 = __hadd2(a2, a6); a3 = __hadd2(a3, a7);
            a0 = __hadd2(a0, a2); a1 = __hadd2(a1, a3);
            a0 = __hadd2(a0, a1);
            float2 f = __half22float2(a0);
            ghb[j]       = bsj + f.x;
            ghb[452 + j] = bsj + f.y;
        }
        __syncthreads();

        if (ge) {
            float hr = ghb[row * 452 + jj];
            float hz = ghb[row * 452 + HH + jj];
            float hn = ghb[row * 452 + 2 * HH + jj];
            float rg = sigm(g_r + hr);
            float zg = sigm(g_z + hz);
            float ng = fast_tanh(g_n + rg * hn);
            float hp = __half2float(reinterpret_cast<const __half*>(h2s)[jj * 2 + row]);
            float hv = (1.f - zg) * ng + zg * hp;
            reinterpret_cast<__half*>(h2s)[jj * 2 + row] = __float2half(hv);
            d_seq[((size_t)(row ? b1 : b0) * TT + t) * (2 * HH) + dir * HH + jj] = hv;
        }
        __syncthreads();
    }
    if (ge) {
        float hv = __half2float(reinterpret_cast<const __half*>(h2s)[jj * 2 + row]);
        d_hidden[(size_t)(row ? b1 : b0) * (2 * HH) + dir * HH + jj] = hv;
    }
}

// ---------------- context ----------------
__global__ void ctx_kernel(const float* __restrict__ Wattn) {
    int bk = blockIdx.x;
    int b = bk / KK, k = bk - b * KK;
    __shared__ float hs[2 * HH];
    int tid = threadIdx.x;
    if (tid < 2 * HH) hs[tid] = d_hidden[b * 2 * HH + tid];
    __syncthreads();
    if (tid < 2 * HH) {
        float acc = d_bias2[k * 2 * HH + tid];
        const float* w = Wattn + ((size_t)k * (CC + 2 * HH) + CC) * (2 * HH) + tid;
        #pragma unroll 4
        for (int c = 0; c < 2 * HH; ++c) acc += hs[c] * w[(size_t)c * (2 * HH)];
        d_context[((size_t)b * KK + k) * (2 * HH) + tid] = tanhf(acc);
    }
}

// ---------------- energy -> softmax(t) -> pooled ----------------
__global__ void pool_kernel() {
    int b = blockIdx.x;
    __shared__ float ctx[KK][2 * HH];
    __shared__ float en[TT][KK];
    int tid = threadIdx.x;
    int w = tid >> 5, lane = tid & 31;
    for (int i = tid; i < KK * 2 * HH; i += 256)
        ctx[i / (2 * HH)][i % (2 * HH)] = d_context[(size_t)b * KK * 2 * HH + i];
    __syncthreads();
    for (int t = w; t < TT; t += 8) {
        const float* srow = d_seq + ((size_t)b * TT + t) * (2 * HH);
        float pk[KK] = {0, 0, 0, 0, 0, 0};
        for (int d = lane; d < 2 * HH; d += 32) {
            float s = srow[d];
            #pragma unroll
            for (int k = 0; k < KK; ++k) pk[k] = fmaf(s, ctx[k][d], pk[k]);
        }
        #pragma unroll
        for (int k = 0; k < KK; ++k) {
            float v = pk[k];
            for (int off = 16; off; off >>= 1) v += __shfl_xor_sync(~0u, v, off);
            if (lane == 0) en[t][k] = v;
        }
    }
    __syncthreads();
    if (w < KK) {
        float mx = -1e30f;
        for (int t = lane; t < TT; t += 32) mx = fmaxf(mx, en[t][w]);
        for (int off = 16; off; off >>= 1) mx = fmaxf(mx, __shfl_xor_sync(~0u, mx, off));
        float sum = 0.f;
        for (int t = lane; t < TT; t += 32) { float e2 = __expf(en[t][w] - mx); en[t][w] = e2; sum += e2; }
        for (int off = 16; off; off >>= 1) sum += __shfl_xor_sync(~0u, sum, off);
        float inv = 1.f / sum;
        for (int t = lane; t < TT; t += 32) en[t][w] *= inv;
    }
    __syncthreads();
    for (int d = tid; d < 2 * HH; d += 256) {
        float acc[KK] = {0, 0, 0, 0, 0, 0};
        for (int t = 0; t < TT; ++t) {
            float s = d_seq[((size_t)b * TT + t) * (2 * HH) + d];
            #pragma unroll
            for (int k = 0; k < KK; ++k) acc[k] = fmaf(s, en[t][k], acc[k]);
        }
        #pragma unroll
        for (int k = 0; k < KK; ++k)
            d_pooled[((size_t)b * KK + k) * (2 * HH) + d] = acc[k];
    }
}

// ---------------- topic -> logits -> softmax ----------------
__global__ void topic_kernel(const float* __restrict__ Wtop, const float* __restrict__ btop,
                             const float* __restrict__ Wout, const float* __restrict__ bout,
                             float* __restrict__ out) {
    int b = blockIdx.x;
    __shared__ float ps[KK * 2 * HH];
    __shared__ float feats[KK * THD];
    __shared__ float lg[CLS];
    int tid = threadIdx.x;
    for (int i = tid; i < KK * 2 * HH; i += 128) ps[i] = d_pooled[(size_t)b * KK * 2 * HH + i];
    __syncthreads();
    if (tid < KK * THD) {
        int k = tid / THD, th = tid - k * THD;
        float acc = btop[tid];
        const float* wp = Wtop + (size_t)k * (2 * HH) * THD + th;
        #pragma unroll 4
        for (int d = 0; d < 2 * HH; ++d) acc += ps[k * 2 * HH + d] * wp[d * THD];
        feats[tid] = fmaxf(acc, 0.f);
    }
    __syncthreads();
    if (tid < CLS) {
        float acc = bout[tid];
        for (int e2 = 0; e2 < KK * THD; ++e2) acc += feats[e2] * Wout[e2 * CLS + tid];
        lg[tid] = acc;
    }
    __syncthreads();
    if (tid < CLS) {
        float mx = lg[0];
        #pragma unroll
        for (int c = 1; c < CLS; ++c) mx = fmaxf(mx, lg[c]);
        float sum = 0.f;
        #pragma unroll
        for (int c = 0; c < CLS; ++c) sum += __expf(lg[c] - mx);
        out[b * CLS + tid] = __expf(lg[tid] - mx) / sum;
    }
}

// ---------------- orthogonality regularizer ----------------
__global__ void reg_partial_kernel() {
    int b = blockIdx.x;
    __shared__ float cs[KK * 2 * HH];
    __shared__ float D[KK * KK];
    int tid = threadIdx.x;
    int w = tid >> 5, lane = tid & 31;
    for (int i = tid; i < KK * 2 * HH; i += 256) cs[i] = d_context[(size_t)b * KK * 2 * HH + i];
    __syncthreads();
    for (int p2 = w; p2 < KK * KK; p2 += 8) {
        int k = p2 / KK, j = p2 - k * KK;
        float v = 0.f;
        for (int d = lane; d < 2 * HH; d += 32) v += cs[k * 2 * HH + d] * cs[j * 2 * HH + d];
        for (int off = 16; off; off >>= 1) v += __shfl_xor_sync(~0u, v, off);
        if (lane == 0) D[p2] = v;
    }
    __syncthreads();
    if (tid == 0) {
        float nk[KK];
        #pragma unroll
        for (int k = 0; k < KK; ++k) nk[k] = fmaxf(sqrtf(D[k * KK + k]), 1e-12f);
        float S = 0.f;
        for (int k = 0; k < KK; ++k)
            for (int j = 0; j < KK; ++j) {
                float g = D[k * KK + j] / (nk[k] * nk[j]) - (k == j ? 1.f : 0.f);
                S += g * g;
            }
        d_regpart[b] = sqrtf(S);
    }
}

__global__ void reg_final_kernel(float* __restrict__ regout) {
    __shared__ float s[BB];
    int tid = threadIdx.x;
    s[tid] = d_regpart[tid];
    __syncthreads();
    for (int off = 64; off; off >>= 1) {
        if (tid < off) s[tid] += s[tid + off];
        __syncthreads();
    }
    if (tid == 0) *regout = s[0] / (float)BB;
}

// ---------------- launch ------------------------------------------------------------------
extern "C" void kernel_launch(void* const* d_in, const int* in_sizes, int n_in,
                              void* d_out, int out_size) {
    const float* x      = (const float*)d_in[0];
    const float* Wih_f  = (const float*)d_in[1];
    const float* Whh_f  = (const float*)d_in[2];
    const float* bih_f  = (const float*)d_in[3];
    const float* bhh_f  = (const float*)d_in[4];
    const float* Wih_b  = (const float*)d_in[5];
    const float* Whh_b  = (const float*)d_in[6];
    const float* bih_b  = (const float*)d_in[7];
    const float* bhh_b  = (const float*)d_in[8];
    const float* attn_c = (const float*)d_in[9];
    const float* Wattn  = (const float*)d_in[10];
    const float* battn  = (const float*)d_in[11];
    const float* Wtop   = (const float*)d_in[12];
    const float* btop   = (const float*)d_in[13];
    const float* Wout   = (const float*)d_in[14];
    const float* bout   = (const float*)d_in[15];
    float* out = (float*)d_out;

    prep_kernel<<<(2 * G3 * WROW + 255) / 256, 256>>>(Whh_f, Whh_b);
    bias2_kernel<<<KK, 320>>>(attn_c, Wattn, battn);

    gemm_gi<<<dim3(8, 512, 2), 256>>>(x, Wih_f, Wih_b, bih_f, bih_b);

    scan_kernel<<<128, 512>>>(bhh_f, bhh_b);

    ctx_kernel<<<BB * KK, 320>>>(Wattn);
    pool_kernel<<<BB, 256>>>();
    topic_kernel<<<BB, 128>>>(Wtop, btop, Wout, bout, out);
    if (out_size > BB * CLS) {
        reg_partial_kernel<<<BB, 256>>>();
        reg_final_kernel<<<1, BB>>>(out + BB * CLS);
    }
}

// round 7
// speedup vs baseline: 5.9842x; 1.2149x over previous
#include <cuda_runtime.h>
#include <cuda_fp16.h>
#include <cstdint>

#define BB   128
#define TT   512
#define II   300
#define HH   150
#define G3   450
#define KK   6
#define CC   300
#define THD  20
#define CLS  5

#define WROW 152
#define KP   320          // padded K for fp16 GEMM inputs
#define MM   (BB * TT)    // 65536

// ---------------- scratch ----------------
__device__ float d_gi_f[(size_t)BB * TT * G3];
__device__ float d_gi_b[(size_t)BB * TT * G3];
__device__ float d_seq [(size_t)BB * TT * 2 * HH];
__device__ float d_hidden[BB * 2 * HH];
__device__ __half d_Whh_h[2][G3 * WROW];
__device__ __half d_Xh[(size_t)MM * KP];
__device__ __half d_Wh[2][512 * KP];
__device__ float d_bias2[KK * 2 * HH];
__device__ float d_context[BB * KK * 2 * HH];
__device__ float d_pooled [BB * KK * 2 * HH];
__device__ float d_regpart[BB];

__device__ __forceinline__ uint32_t smem_u32(const void* p) {
    uint32_t r;
    asm("{ .reg .u64 t; cvta.to.shared.u64 t, %1; cvt.u32.u64 %0, t; }" : "=r"(r) : "l"(p));
    return r;
}

// ---------------- prep: Whh -> half [j][i] (for scan) ----------------
__global__ void prep_kernel(const float* __restrict__ Whh_f, const float* __restrict__ Whh_b) {
    int idx = blockIdx.x * blockDim.x + threadIdx.x;
    int tot = G3 * WROW;
    if (idx < 2 * tot) {
        int d = idx / tot;
        int r = idx - d * tot;
        int j = r / WROW, i = r - j * WROW;
        const float* W = d ? Whh_b : Whh_f;
        d_Whh_h[d][r] = (i < HH) ? __float2half(W[j * HH + i]) : __float2half(0.f);
    }
}

// ---------------- convert X, Wih -> padded half ----------------
__global__ void convert_kernel(const float* __restrict__ X,
                               const float* __restrict__ Wf, const float* __restrict__ Wb) {
    int idx = blockIdx.x * blockDim.x + threadIdx.x;    // half2 pair index
    const int totX = MM * (KP / 2);                     // 10.49M
    if (idx < totX) {
        int m = idx / (KP / 2), kp = idx - m * (KP / 2);
        int k = kp * 2;
        float a = (k < II)     ? X[(size_t)m * II + k]     : 0.f;
        float b = (k + 1 < II) ? X[(size_t)m * II + k + 1] : 0.f;
        reinterpret_cast<__half2*>(d_Xh)[idx] = __floats2half2_rn(a, b);
    } else {
        int r = idx - totX;
        const int totW = 512 * (KP / 2);
        if (r < 2 * totW) {
            int d = r / totW;
            int rr = r - d * totW;
            int n = rr / (KP / 2), kp = rr - n * (KP / 2);
            int k = kp * 2;
            const float* W = d ? Wb : Wf;
            float a = (n < G3 && k < II)     ? W[(size_t)n * II + k]     : 0.f;
            float b = (n < G3 && k + 1 < II) ? W[(size_t)n * II + k + 1] : 0.f;
            reinterpret_cast<__half2*>(d_Wh[d])[rr] = __floats2half2_rn(a, b);
        }
    }
}

// ---------------- bias2 ----------------
__global__ void bias2_kernel(const float* __restrict__ ac, const float* __restrict__ Wattn,
                             const float* __restrict__ battn) {
    int k = blockIdx.x;
    __shared__ float as[CC];
    int tid = threadIdx.x;
    if (tid < CC) as[tid] = ac[k * CC + tid];
    __syncthreads();
    if (tid < 2 * HH) {
        float acc = battn[k * 2 * HH + tid];
        const float* w = Wattn + (size_t)k * (CC + 2 * HH) * (2 * HH) + tid;
        #pragma unroll 4
        for (int c = 0; c < CC; ++c) acc += as[c] * w[(size_t)c * (2 * HH)];
        d_bias2[k * 2 * HH + tid] = acc;
    }
}

// ---------------- gi GEMM: cp.async + ldmatrix + mma m16n8k16 ----------------------------
// BM=128 BN=64 BK=32, 256 threads (8 warps: 4 M x 2 N), 2-stage cp.async pipeline.
// smem rows padded to 40 halves (80 B) -> conflict-free LDSM phases.
__global__ void __launch_bounds__(256, 2)
gemm_gi(const float* __restrict__ bf, const float* __restrict__ bb) {
    __shared__ __align__(16) __half Asm[2][128 * 40];
    __shared__ __align__(16) __half Bsm[2][64 * 40];
    int which = blockIdx.z;
    const __half* Wh  = d_Wh[which];
    const float* bias = which ? bb : bf;
    float* O          = which ? d_gi_b : d_gi_f;

    int m0 = blockIdx.y * 128;
    int n0 = blockIdx.x * 64;
    int tid = threadIdx.x;
    int wid = tid >> 5, lane = tid & 31;
    int warpM = (wid & 3) * 32;
    int warpN = (wid >> 2) * 32;
    int gr = lane >> 2, t4 = lane & 3;

    float acc[2][4][4];
    #pragma unroll
    for (int mt = 0; mt < 2; ++mt)
        #pragma unroll
        for (int nt = 0; nt < 4; ++nt)
            #pragma unroll
            for (int q = 0; q < 4; ++q) acc[mt][nt][q] = 0.f;

    // cp.async source/dest mapping
    int ar = tid >> 1, ac = (tid & 1) * 2;    // A: row ar, chunks ac, ac+1 (16B each)
    int br = tid >> 2, bc = tid & 3;          // B: row br, chunk bc
    const __half* Xsrc = d_Xh + (size_t)(m0 + ar) * KP + ac * 8;
    const __half* Wsrc = Wh   + (size_t)(n0 + br) * KP + bc * 8;
    uint32_t aBase = smem_u32(&Asm[0][0]);
    uint32_t bBase = smem_u32(&Bsm[0][0]);
    const uint32_t aBuf = 128 * 40 * 2, bBuf = 64 * 40 * 2;
    uint32_t aDst = aBase + (ar * 40 + ac * 8) * 2;
    uint32_t bDst = bBase + (br * 40 + bc * 8) * 2;

    const int NT = KP / 32;   // 10

    auto issue = [&](int it) {
        int buf = it & 1;
        const __half* as_ = Xsrc + it * 32;
        const __half* bs_ = Wsrc + it * 32;
        uint32_t ad = aDst + buf * aBuf;
        uint32_t bd = bDst + buf * bBuf;
        asm volatile(
            "cp.async.cg.shared.global [%0], [%1], 16;\n\t"
            "cp.async.cg.shared.global [%2], [%3], 16;\n\t"
            "cp.async.cg.shared.global [%4], [%5], 16;\n\t"
            "cp.async.commit_group;"
            :: "r"(ad), "l"(as_), "r"(ad + 16), "l"(as_ + 8), "r"(bd), "l"(bs_)
            : "memory");
    };

    // ldmatrix per-lane row offsets (in halves, kk added later)
    uint32_t aRow[2], bRow[2];
    #pragma unroll
    for (int mt = 0; mt < 2; ++mt)
        aRow[mt] = ((warpM + mt * 16 + (lane & 15)) * 40 + ((lane >> 4) * 8)) * 2;
    #pragma unroll
    for (int p2 = 0; p2 < 2; ++p2)
        bRow[p2] = ((warpN + p2 * 16 + ((lane & 16) ? 8 : 0) + (lane & 7)) * 40
                    + ((lane & 8) ? 8 : 0)) * 2;

    issue(0);
    issue(1);

    for (int it = 0; it < NT; ++it) {
        if (it < NT - 1) asm volatile("cp.async.wait_group 1;" ::: "memory");
        else             asm volatile("cp.async.wait_group 0;" ::: "memory");
        __syncthreads();
        int buf = it & 1;
        uint32_t aB = aBase + buf * aBuf;
        uint32_t bB = bBase + buf * bBuf;
        #pragma unroll
        for (int kk = 0; kk < 32; kk += 16) {
            uint32_t a[2][4], b[2][4];
            #pragma unroll
            for (int mt = 0; mt < 2; ++mt)
                asm volatile("ldmatrix.sync.aligned.m8n8.x4.shared.b16 {%0,%1,%2,%3}, [%4];"
                             : "=r"(a[mt][0]), "=r"(a[mt][1]), "=r"(a[mt][2]), "=r"(a[mt][3])
                             : "r"(aB + aRow[mt] + kk * 2));
            #pragma unroll
            for (int p2 = 0; p2 < 2; ++p2)
                asm volatile("ldmatrix.sync.aligned.m8n8.x4.shared.b16 {%0,%1,%2,%3}, [%4];"
                             : "=r"(b[p2][0]), "=r"(b[p2][1]), "=r"(b[p2][2]), "=r"(b[p2][3])
                             : "r"(bB + bRow[p2] + kk * 2));
            #pragma unroll
            for (int mt = 0; mt < 2; ++mt)
                #pragma unroll
                for (int nt = 0; nt < 4; ++nt) {
                    uint32_t b0 = b[nt >> 1][(nt & 1) * 2];
                    uint32_t b1 = b[nt >> 1][(nt & 1) * 2 + 1];
                    asm volatile(
                        "mma.sync.aligned.m16n8k16.row.col.f32.f16.f16.f32 "
                        "{%0,%1,%2,%3}, {%4,%5,%6,%7}, {%8,%9}, {%0,%1,%2,%3};"
                        : "+f"(acc[mt][nt][0]), "+f"(acc[mt][nt][1]),
                          "+f"(acc[mt][nt][2]), "+f"(acc[mt][nt][3])
                        : "r"(a[mt][0]), "r"(a[mt][1]), "r"(a[mt][2]), "r"(a[mt][3]),
                          "r"(b0), "r"(b1));
                }
        }
        __syncthreads();
        if (it + 2 < NT) issue(it + 2);
    }

    #pragma unroll
    for (int mt = 0; mt < 2; ++mt) {
        #pragma unroll
        for (int hf = 0; hf < 2; ++hf) {
            int m = m0 + warpM + mt * 16 + gr + hf * 8;
            float* Orow = O + (size_t)m * G3;
            #pragma unroll
            for (int nt = 0; nt < 4; ++nt) {
                int col = n0 + warpN + nt * 8 + 2 * t4;
                if (col < G3) {
                    float v0 = acc[mt][nt][hf * 2 + 0] + bias[col];
                    float v1 = acc[mt][nt][hf * 2 + 1] + bias[col + 1];
                    *reinterpret_cast<float2*>(Orow + col) = make_float2(v0, v1);
                }
            }
        }
    }
}

// ---------------- persistent bidirectional GRU scan (unchanged) --------------------------
__device__ __forceinline__ float sigm(float x) { return 1.f / (1.f + __expf(-x)); }
__device__ __forceinline__ float fast_tanh(float x) {
    float y; asm("tanh.approx.f32 %0, %1;" : "=f"(y) : "f"(x)); return y;
}

__global__ void __launch_bounds__(512, 1)
scan_kernel(const float* __restrict__ bhh_f, const float* __restrict__ bhh_b) {
    __shared__ __align__(16) __half2 h2s[WROW];
    __shared__ float ghb[2 * 452];
    __shared__ float bsm[G3];

    int bb  = blockIdx.x;
    int dir = bb >> 6;
    int p   = bb & 63;
    int b0  = 2 * p, b1 = b0 + 1;
    const float* gi  = dir ? d_gi_b : d_gi_f;
    const float* bhh = dir ? bhh_b : bhh_f;
    int tid = threadIdx.x;

    for (int i = tid; i < WROW; i += 512) h2s[i] = __floats2half2_rn(0.f, 0.f);
    for (int i = tid; i < G3; i += 512) bsm[i] = bhh[i];

    const int j = tid;
    const bool act = (j < G3);

    __half2 wr[76];
    if (act) {
        const uint4* wrow = reinterpret_cast<const uint4*>(d_Whh_h[dir] + (size_t)j * WROW);
        #pragma unroll
        for (int cdx = 0; cdx < 19; ++cdx) {
            uint4 v = wrow[cdx];
            wr[4 * cdx + 0] = *reinterpret_cast<__half2*>(&v.x);
            wr[4 * cdx + 1] = *reinterpret_cast<__half2*>(&v.y);
            wr[4 * cdx + 2] = *reinterpret_cast<__half2*>(&v.z);
            wr[4 * cdx + 3] = *reinterpret_cast<__half2*>(&v.w);
        }
    }
    __syncthreads();
    float bsj = act ? bsm[j] : 0.f;

    const int e = tid;
    const bool ge = (e < 2 * HH);
    const int row = (e < HH) ? 0 : 1;
    const int jj  = e - row * HH;

    const float4* h4 = reinterpret_cast<const float4*>(h2s);

    for (int s = 0; s < TT; ++s) {
        int t = dir ? (TT - 1 - s) : s;
        float g_r = 0.f, g_z = 0.f, g_n = 0.f;
        if (ge) {
            size_t gbase = ((size_t)(row ? b1 : b0) * TT + t) * G3 + jj;
            g_r = gi[gbase]; g_z = gi[gbase + HH]; g_n = gi[gbase + 2 * HH];
        }

        if (act) {
            __half2 a0 = __floats2half2_rn(0.f, 0.f), a1 = a0, a2 = a0, a3 = a0;
            __half2 a4 = a0, a5 = a0, a6 = a0, a7 = a0;
            #pragma unroll
            for (int cdx = 0; cdx < 19; ++cdx) {
                float4 hva = h4[2 * cdx];
                float4 hvb = h4[2 * cdx + 1];
                const __half2* hha = reinterpret_cast<const __half2*>(&hva);
                const __half2* hhb = reinterpret_cast<const __half2*>(&hvb);
                __half2 w0 = wr[4 * cdx + 0], w1 = wr[4 * cdx + 1];
                __half2 w2 = wr[4 * cdx + 2], w3 = wr[4 * cdx + 3];
                a0 = __hfma2(__low2half2 (w0), hha[0], a0);
                a1 = __hfma2(__high2half2(w0), hha[1], a1);
                a2 = __hfma2(__low2half2 (w1), hha[2], a2);
                a3 = __hfma2(__high2half2(w1), hha[3], a3);
                a4 = __hfma2(__low2half2 (w2), hhb[0], a4);
                a5 = __hfma2(__high2half2(w2), hhb[1], a5);
                a6 = __hfma2(__low2half2 (w3), hhb[2], a6);
                a7 = __hfma2(__high2half2(w3), hhb[3], a7);
            }
            a0 = __hadd2(a0, a4); a1 = __hadd2(a1, a5);
            a2 = __hadd2(a2, a6); a3 = __hadd2(a3, a7);
            a0 = __hadd2(a0, a2); a1 = __hadd2(a1, a3);
            a0 = __hadd2(a0, a1);
            float2 f = __half22float2(a0);
            ghb[j]       = bsj + f.x;
            ghb[452 + j] = bsj + f.y;
        }
        __syncthreads();

        if (ge) {
            float hr = ghb[row * 452 + jj];
            float hz = ghb[row * 452 + HH + jj];
            float hn = ghb[row * 452 + 2 * HH + jj];
            float rg = sigm(g_r + hr);
            float zg = sigm(g_z + hz);
            float ng = fast_tanh(g_n + rg * hn);
            float hp = __half2float(reinterpret_cast<const __half*>(h2s)[jj * 2 + row]);
            float hv = (1.f - zg) * ng + zg * hp;
            reinterpret_cast<__half*>(h2s)[jj * 2 + row] = __float2half(hv);
            d_seq[((size_t)(row ? b1 : b0) * TT + t) * (2 * HH) + dir * HH + jj] = hv;
        }
        __syncthreads();
    }
    if (ge) {
        float hv = __half2float(reinterpret_cast<const __half*>(h2s)[jj * 2 + row]);
        d_hidden[(size_t)(row ? b1 : b0) * (2 * HH) + dir * HH + jj] = hv;
    }
}

// ---------------- context ----------------
__global__ void ctx_kernel(const float* __restrict__ Wattn) {
    int bk = blockIdx.x;
    int b = bk / KK, k = bk - b * KK;
    __shared__ float hs[2 * HH];
    int tid = threadIdx.x;
    if (tid < 2 * HH) hs[tid] = d_hidden[b * 2 * HH + tid];
    __syncthreads();
    if (tid < 2 * HH) {
        float acc = d_bias2[k * 2 * HH + tid];
        const float* w = Wattn + ((size_t)k * (CC + 2 * HH) + CC) * (2 * HH) + tid;
        #pragma unroll 4
        for (int c = 0; c < 2 * HH; ++c) acc += hs[c] * w[(size_t)c * (2 * HH)];
        d_context[((size_t)b * KK + k) * (2 * HH) + tid] = tanhf(acc);
    }
}

// ---------------- energy -> softmax(t) -> pooled (512 threads) ----------------
__global__ void pool_kernel() {
    int b = blockIdx.x;
    __shared__ float ctx[KK][2 * HH];
    __shared__ float en[TT][KK];
    int tid = threadIdx.x;              // 512
    int w = tid >> 5, lane = tid & 31;
    for (int i = tid; i < KK * 2 * HH; i += 512)
        ctx[i / (2 * HH)][i % (2 * HH)] = d_context[(size_t)b * KK * 2 * HH + i];
    __syncthreads();
    for (int t = w; t < TT; t += 16) {
        const float* srow = d_seq + ((size_t)b * TT + t) * (2 * HH);
        float pk[KK] = {0, 0, 0, 0, 0, 0};
        for (int d = lane; d < 2 * HH; d += 32) {
            float s = srow[d];
            #pragma unroll
            for (int k = 0; k < KK; ++k) pk[k] = fmaf(s, ctx[k][d], pk[k]);
        }
        #pragma unroll
        for (int k = 0; k < KK; ++k) {
            float v = pk[k];
            for (int off = 16; off; off >>= 1) v += __shfl_xor_sync(~0u, v, off);
            if (lane == 0) en[t][k] = v;
        }
    }
    __syncthreads();
    if (w < KK) {
        float mx = -1e30f;
        for (int t = lane; t < TT; t += 32) mx = fmaxf(mx, en[t][w]);
        for (int off = 16; off; off >>= 1) mx = fmaxf(mx, __shfl_xor_sync(~0u, mx, off));
        float sum = 0.f;
        for (int t = lane; t < TT; t += 32) { float e2 = __expf(en[t][w] - mx); en[t][w] = e2; sum += e2; }
        for (int off = 16; off; off >>= 1) sum += __shfl_xor_sync(~0u, sum, off);
        float inv = 1.f / sum;
        for (int t = lane; t < TT; t += 32) en[t][w] *= inv;
    }
    __syncthreads();
    for (int d = tid; d < 2 * HH; d += 512) {
        float acc[KK] = {0, 0, 0, 0, 0, 0};
        for (int t = 0; t < TT; ++t) {
            float s = d_seq[((size_t)b * TT + t) * (2 * HH) + d];
            #pragma unroll
            for (int k = 0; k < KK; ++k) acc[k] = fmaf(s, en[t][k], acc[k]);
        }
        #pragma unroll
        for (int k = 0; k < KK; ++k)
            d_pooled[((size_t)b * KK + k) * (2 * HH) + d] = acc[k];
    }
}

// ---------------- topic -> logits -> softmax ----------------
__global__ void topic_kernel(const float* __restrict__ Wtop, const float* __restrict__ btop,
                             const float* __restrict__ Wout, const float* __restrict__ bout,
                             float* __restrict__ out) {
    int b = blockIdx.x;
    __shared__ float ps[KK * 2 * HH];
    __shared__ float feats[KK * THD];
    __shared__ float lg[CLS];
    int tid = threadIdx.x;
    for (int i = tid; i < KK * 2 * HH; i += 128) ps[i] = d_pooled[(size_t)b * KK * 2 * HH + i];
    __syncthreads();
    if (tid < KK * THD) {
        int k = tid / THD, th = tid - k * THD;
        float acc = btop[tid];
        const float* wp = Wtop + (size_t)k * (2 * HH) * THD + th;
        #pragma unroll 4
        for (int d = 0; d < 2 * HH; ++d) acc += ps[k * 2 * HH + d] * wp[d * THD];
        feats[tid] = fmaxf(acc, 0.f);
    }
    __syncthreads();
    if (tid < CLS) {
        float acc = bout[tid];
        for (int e2 = 0; e2 < KK * THD; ++e2) acc += feats[e2] * Wout[e2 * CLS + tid];
        lg[tid] = acc;
    }
    __syncthreads();
    if (tid < CLS) {
        float mx = lg[0];
        #pragma unroll
        for (int c = 1; c < CLS; ++c) mx = fmaxf(mx, lg[c]);
        float sum = 0.f;
        #pragma unroll
        for (int c = 0; c < CLS; ++c) sum += __expf(lg[c] - mx);
        out[b * CLS + tid] = __expf(lg[tid] - mx) / sum;
    }
}

// ---------------- orthogonality regularizer ----------------
__global__ void reg_partial_kernel() {
    int b = blockIdx.x;
    __shared__ float cs[KK * 2 * HH];
    __shared__ float D[KK * KK];
    int tid = threadIdx.x;
    int w = tid >> 5, lane = tid & 31;
    for (int i = tid; i < KK * 2 * HH; i += 256) cs[i] = d_context[(size_t)b * KK * 2 * HH + i];
    __syncthreads();
    for (int p2 = w; p2 < KK * KK; p2 += 8) {
        int k = p2 / KK, j = p2 - k * KK;
        float v = 0.f;
        for (int d = lane; d < 2 * HH; d += 32) v += cs[k * 2 * HH + d] * cs[j * 2 * HH + d];
        for (int off = 16; off; off >>= 1) v += __shfl_xor_sync(~0u, v, off);
        if (lane == 0) D[p2] = v;
    }
    __syncthreads();
    if (tid == 0) {
        float nk[KK];
        #pragma unroll
        for (int k = 0; k < KK; ++k) nk[k] = fmaxf(sqrtf(D[k * KK + k]), 1e-12f);
        float S = 0.f;
        for (int k = 0; k < KK; ++k)
            for (int j = 0; j < KK; ++j) {
                float g = D[k * KK + j] / (nk[k] * nk[j]) - (k == j ? 1.f : 0.f);
                S += g * g;
            }
        d_regpart[b] = sqrtf(S);
    }
}

__global__ void reg_final_kernel(float* __restrict__ regout) {
    __shared__ float s[BB];
    int tid = threadIdx.x;
    s[tid] = d_regpart[tid];
    __syncthreads();
    for (int off = 64; off; off >>= 1) {
        if (tid < off) s[tid] += s[tid + off];
        __syncthreads();
    }
    if (tid == 0) *regout = s[0] / (float)BB;
}

// ---------------- launch ------------------------------------------------------------------
extern "C" void kernel_launch(void* const* d_in, const int* in_sizes, int n_in,
                              void* d_out, int out_size) {
    const float* x      = (const float*)d_in[0];
    const float* Wih_f  = (const float*)d_in[1];
    const float* Whh_f  = (const float*)d_in[2];
    const float* bih_f  = (const float*)d_in[3];
    const float* bhh_f  = (const float*)d_in[4];
    const float* Wih_b  = (const float*)d_in[5];
    const float* Whh_b  = (const float*)d_in[6];
    const float* bih_b  = (const float*)d_in[7];
    const float* bhh_b  = (const float*)d_in[8];
    const float* attn_c = (const float*)d_in[9];
    const float* Wattn  = (const float*)d_in[10];
    const float* battn  = (const float*)d_in[11];
    const float* Wtop   = (const float*)d_in[12];
    const float* btop   = (const float*)d_in[13];
    const float* Wout   = (const float*)d_in[14];
    const float* bout   = (const float*)d_in[15];
    float* out = (float*)d_out;

    prep_kernel<<<(2 * G3 * WROW + 255) / 256, 256>>>(Whh_f, Whh_b);
    const int npair = MM * (KP / 2) + 2 * 512 * (KP / 2);
    convert_kernel<<<(npair + 255) / 256, 256>>>(x, Wih_f, Wih_b);
    bias2_kernel<<<KK, 320>>>(attn_c, Wattn, battn);

    gemm_gi<<<dim3(8, 512, 2), 256>>>(bih_f, bih_b);

    scan_kernel<<<128, 512>>>(bhh_f, bhh_b);

    ctx_kernel<<<BB * KK, 320>>>(Wattn);
    pool_kernel<<<BB, 512>>>();
    topic_kernel<<<BB, 128>>>(Wtop, btop, Wout, bout, out);
    if (out_size > BB * CLS) {
        reg_partial_kernel<<<BB, 256>>>();
        reg_final_kernel<<<1, BB>>>(out + BB * CLS);
    }
}

// round 8
// speedup vs baseline: 7.1437x; 1.1938x over previous
#include <cuda_runtime.h>
#include <cuda_fp16.h>
#include <cstdint>

#define BB   128
#define TT   512
#define II   300
#define HH   150
#define G3   450
#define KK   6
#define CC   300
#define THD  20
#define CLS  5

#define KP   320          // padded K for fp16 GEMM inputs
#define MM   (BB * TT)    // 65536

#define JPAD  464         // 29 m-tiles of 16 (450 padded)
#define KPAD2 160         // 10 k-tiles of 16 (150 padded)
#define MTILES 29

// ---------------- scratch ----------------
__device__ float d_gi_f[(size_t)BB * TT * G3];
__device__ float d_gi_b[(size_t)BB * TT * G3];
__device__ float d_seq [(size_t)BB * TT * 2 * HH];
__device__ float d_hidden[BB * 2 * HH];
__device__ __half d_Whh_h[2][JPAD * KPAD2];
__device__ __half d_Xh[(size_t)MM * KP];
__device__ __half d_Wh[2][512 * KP];
__device__ float d_bias2[KK * 2 * HH];
__device__ float d_context[BB * KK * 2 * HH];
__device__ float d_pooled [BB * KK * 2 * HH];
__device__ float d_regpart[BB];

__device__ __forceinline__ uint32_t smem_u32(const void* p) {
    uint32_t r;
    asm("{ .reg .u64 t; cvta.to.shared.u64 t, %1; cvt.u32.u64 %0, t; }" : "=r"(r) : "l"(p));
    return r;
}

__device__ __forceinline__ void mma16816(float* d, const uint32_t* a, uint32_t b0, uint32_t b1) {
    asm volatile(
        "mma.sync.aligned.m16n8k16.row.col.f32.f16.f16.f32 "
        "{%0,%1,%2,%3}, {%4,%5,%6,%7}, {%8,%9}, {%0,%1,%2,%3};"
        : "+f"(d[0]), "+f"(d[1]), "+f"(d[2]), "+f"(d[3])
        : "r"(a[0]), "r"(a[1]), "r"(a[2]), "r"(a[3]), "r"(b0), "r"(b1));
}

// ---------------- prep: Whh -> half [JPAD][KPAD2], zero padded ----------------
__global__ void prep_kernel(const float* __restrict__ Whh_f, const float* __restrict__ Whh_b) {
    int idx = blockIdx.x * blockDim.x + threadIdx.x;
    int tot = JPAD * KPAD2;
    if (idx < 2 * tot) {
        int d = idx / tot;
        int r = idx - d * tot;
        int j = r / KPAD2, i = r - j * KPAD2;
        const float* W = d ? Whh_b : Whh_f;
        d_Whh_h[d][r] = (j < G3 && i < HH) ? __float2half(W[j * HH + i]) : __float2half(0.f);
    }
}

// ---------------- convert X, Wih -> padded half ----------------
__global__ void convert_kernel(const float* __restrict__ X,
                               const float* __restrict__ Wf, const float* __restrict__ Wb) {
    int idx = blockIdx.x * blockDim.x + threadIdx.x;
    const int totX = MM * (KP / 2);
    if (idx < totX) {
        int m = idx / (KP / 2), kp = idx - m * (KP / 2);
        int k = kp * 2;
        float a = (k < II)     ? X[(size_t)m * II + k]     : 0.f;
        float b = (k + 1 < II) ? X[(size_t)m * II + k + 1] : 0.f;
        reinterpret_cast<__half2*>(d_Xh)[idx] = __floats2half2_rn(a, b);
    } else {
        int r = idx - totX;
        const int totW = 512 * (KP / 2);
        if (r < 2 * totW) {
            int d = r / totW;
            int rr = r - d * totW;
            int n = rr / (KP / 2), kp = rr - n * (KP / 2);
            int k = kp * 2;
            const float* W = d ? Wb : Wf;
            float a = (n < G3 && k < II)     ? W[(size_t)n * II + k]     : 0.f;
            float b = (n < G3 && k + 1 < II) ? W[(size_t)n * II + k + 1] : 0.f;
            reinterpret_cast<__half2*>(d_Wh[d])[rr] = __floats2half2_rn(a, b);
        }
    }
}

// ---------------- bias2 ----------------
__global__ void bias2_kernel(const float* __restrict__ ac, const float* __restrict__ Wattn,
                             const float* __restrict__ battn) {
    int k = blockIdx.x;
    __shared__ float as[CC];
    int tid = threadIdx.x;
    if (tid < CC) as[tid] = ac[k * CC + tid];
    __syncthreads();
    if (tid < 2 * HH) {
        float acc = battn[k * 2 * HH + tid];
        const float* w = Wattn + (size_t)k * (CC + 2 * HH) * (2 * HH) + tid;
        #pragma unroll 4
        for (int c = 0; c < CC; ++c) acc += as[c] * w[(size_t)c * (2 * HH)];
        d_bias2[k * 2 * HH + tid] = acc;
    }
}

// ---------------- gi GEMM: cp.async + ldmatrix + mma m16n8k16 (unchanged) -----------------
__global__ void __launch_bounds__(256, 2)
gemm_gi(const float* __restrict__ bf, const float* __restrict__ bb) {
    __shared__ __align__(16) __half Asm[2][128 * 40];
    __shared__ __align__(16) __half Bsm[2][64 * 40];
    int which = blockIdx.z;
    const __half* Wh  = d_Wh[which];
    const float* bias = which ? bb : bf;
    float* O          = which ? d_gi_b : d_gi_f;

    int m0 = blockIdx.y * 128;
    int n0 = blockIdx.x * 64;
    int tid = threadIdx.x;
    int wid = tid >> 5, lane = tid & 31;
    int warpM = (wid & 3) * 32;
    int warpN = (wid >> 2) * 32;
    int gr = lane >> 2, t4 = lane & 3;

    float acc[2][4][4];
    #pragma unroll
    for (int mt = 0; mt < 2; ++mt)
        #pragma unroll
        for (int nt = 0; nt < 4; ++nt)
            #pragma unroll
            for (int q = 0; q < 4; ++q) acc[mt][nt][q] = 0.f;

    int ar = tid >> 1, ac = (tid & 1) * 2;
    int br = tid >> 2, bc = tid & 3;
    const __half* Xsrc = d_Xh + (size_t)(m0 + ar) * KP + ac * 8;
    const __half* Wsrc = Wh   + (size_t)(n0 + br) * KP + bc * 8;
    uint32_t aBase = smem_u32(&Asm[0][0]);
    uint32_t bBase = smem_u32(&Bsm[0][0]);
    const uint32_t aBuf = 128 * 40 * 2, bBuf = 64 * 40 * 2;
    uint32_t aDst = aBase + (ar * 40 + ac * 8) * 2;
    uint32_t bDst = bBase + (br * 40 + bc * 8) * 2;

    const int NT = KP / 32;

    auto issue = [&](int it) {
        int buf = it & 1;
        const __half* as_ = Xsrc + it * 32;
        const __half* bs_ = Wsrc + it * 32;
        uint32_t ad = aDst + buf * aBuf;
        uint32_t bd = bDst + buf * bBuf;
        asm volatile(
            "cp.async.cg.shared.global [%0], [%1], 16;\n\t"
            "cp.async.cg.shared.global [%2], [%3], 16;\n\t"
            "cp.async.cg.shared.global [%4], [%5], 16;\n\t"
            "cp.async.commit_group;"
            :: "r"(ad), "l"(as_), "r"(ad + 16), "l"(as_ + 8), "r"(bd), "l"(bs_)
            : "memory");
    };

    uint32_t aRow[2], bRow[2];
    #pragma unroll
    for (int mt = 0; mt < 2; ++mt)
        aRow[mt] = ((warpM + mt * 16 + (lane & 15)) * 40 + ((lane >> 4) * 8)) * 2;
    #pragma unroll
    for (int p2 = 0; p2 < 2; ++p2)
        bRow[p2] = ((warpN + p2 * 16 + ((lane & 16) ? 8 : 0) + (lane & 7)) * 40
                    + ((lane & 8) ? 8 : 0)) * 2;

    issue(0);
    issue(1);

    for (int it = 0; it < NT; ++it) {
        if (it < NT - 1) asm volatile("cp.async.wait_group 1;" ::: "memory");
        else             asm volatile("cp.async.wait_group 0;" ::: "memory");
        __syncthreads();
        int buf = it & 1;
        uint32_t aB = aBase + buf * aBuf;
        uint32_t bB = bBase + buf * bBuf;
        #pragma unroll
        for (int kk = 0; kk < 32; kk += 16) {
            uint32_t a[2][4], b[2][4];
            #pragma unroll
            for (int mt = 0; mt < 2; ++mt)
                asm volatile("ldmatrix.sync.aligned.m8n8.x4.shared.b16 {%0,%1,%2,%3}, [%4];"
                             : "=r"(a[mt][0]), "=r"(a[mt][1]), "=r"(a[mt][2]), "=r"(a[mt][3])
                             : "r"(aB + aRow[mt] + kk * 2));
            #pragma unroll
            for (int p2 = 0; p2 < 2; ++p2)
                asm volatile("ldmatrix.sync.aligned.m8n8.x4.shared.b16 {%0,%1,%2,%3}, [%4];"
                             : "=r"(b[p2][0]), "=r"(b[p2][1]), "=r"(b[p2][2]), "=r"(b[p2][3])
                             : "r"(bB + bRow[p2] + kk * 2));
            #pragma unroll
            for (int mt = 0; mt < 2; ++mt)
                #pragma unroll
                for (int nt = 0; nt < 4; ++nt) {
                    uint32_t b0 = b[nt >> 1][(nt & 1) * 2];
                    uint32_t b1 = b[nt >> 1][(nt & 1) * 2 + 1];
                    asm volatile(
                        "mma.sync.aligned.m16n8k16.row.col.f32.f16.f16.f32 "
                        "{%0,%1,%2,%3}, {%4,%5,%6,%7}, {%8,%9}, {%0,%1,%2,%3};"
                        : "+f"(acc[mt][nt][0]), "+f"(acc[mt][nt][1]),
                          "+f"(acc[mt][nt][2]), "+f"(acc[mt][nt][3])
                        : "r"(a[mt][0]), "r"(a[mt][1]), "r"(a[mt][2]), "r"(a[mt][3]),
                          "r"(b0), "r"(b1));
                }
        }
        __syncthreads();
        if (it + 2 < NT) issue(it + 2);
    }

    #pragma unroll
    for (int mt = 0; mt < 2; ++mt) {
        #pragma unroll
        for (int hf = 0; hf < 2; ++hf) {
            int m = m0 + warpM + mt * 16 + gr + hf * 8;
            float* Orow = O + (size_t)m * G3;
            #pragma unroll
            for (int nt = 0; nt < 4; ++nt) {
                int col = n0 + warpN + nt * 8 + 2 * t4;
                if (col < G3) {
                    float v0 = acc[mt][nt][hf * 2 + 0] + bias[col];
                    float v1 = acc[mt][nt][hf * 2 + 1] + bias[col + 1];
                    *reinterpret_cast<float2*>(Orow + col) = make_float2(v0, v1);
                }
            }
        }
    }
}

// ---------------- persistent bidirectional GRU scan: tensor-core matvec ------------------
// 512 threads (16 warps). gh[464x2] = Whh[464x160] x h[160x2] via mma.m16n8k16.
// A (Whh) fragments register-resident; B (h) rebuilt per step from smem (2 LDS.32/lane);
// D initialized from bias fragments; stored by tig==0 lanes as float2 (row0,row1).
__device__ __forceinline__ float sigm(float x) { return 1.f / (1.f + __expf(-x)); }
__device__ __forceinline__ float fast_tanh(float x) {
    float y; asm("tanh.approx.f32 %0, %1;" : "=f"(y) : "f"(x)); return y;
}

__global__ void __launch_bounds__(512, 1)
scan_kernel(const float* __restrict__ bhh_f, const float* __restrict__ bhh_b) {
    __shared__ __align__(8) float2 ghb2[JPAD];        // (row0,row1) per j
    __shared__ __align__(4) __half h_s[2][KPAD2];     // h per batch row, k-padded zeros

    int bb  = blockIdx.x;
    int dir = bb >> 6;
    int p   = bb & 63;
    int b0  = 2 * p, b1 = b0 + 1;
    const float* gi  = dir ? d_gi_b : d_gi_f;
    const float* bhh = dir ? bhh_b : bhh_f;
    const __half* Wd = d_Whh_h[dir];
    int tid = threadIdx.x;              // 512
    int wid = tid >> 5, lane = tid & 31;
    int g = lane >> 2, tig = lane & 3;

    // zero h (incl. k padding 150..159 which must stay zero)
    for (int i = tid; i < 2 * KPAD2; i += 512)
        reinterpret_cast<__half*>(h_s)[i] = __float2half(0.f);

    // tile assignment: warp wid owns m-tiles t1=wid and t2=16+wid (if <29)
    const int t1 = wid;
    const int t2 = 16 + wid;
    const bool has2 = (t2 < MTILES);

    // A fragments (constant across steps)
    uint32_t A1[10][4], A2[10][4];
    {
        const __half* r0 = Wd + (size_t)(t1 * 16 + g) * KPAD2;        // row g
        const __half* r8 = r0 + 8 * KPAD2;                            // row g+8
        #pragma unroll
        for (int kt = 0; kt < 10; ++kt) {
            int k0 = kt * 16 + tig * 2;
            A1[kt][0] = *reinterpret_cast<const uint32_t*>(r0 + k0);
            A1[kt][1] = *reinterpret_cast<const uint32_t*>(r8 + k0);
            A1[kt][2] = *reinterpret_cast<const uint32_t*>(r0 + k0 + 8);
            A1[kt][3] = *reinterpret_cast<const uint32_t*>(r8 + k0 + 8);
        }
        if (has2) {
            const __half* s0 = Wd + (size_t)(t2 * 16 + g) * KPAD2;
            const __half* s8 = s0 + 8 * KPAD2;
            #pragma unroll
            for (int kt = 0; kt < 10; ++kt) {
                int k0 = kt * 16 + tig * 2;
                A2[kt][0] = *reinterpret_cast<const uint32_t*>(s0 + k0);
                A2[kt][1] = *reinterpret_cast<const uint32_t*>(s8 + k0);
                A2[kt][2] = *reinterpret_cast<const uint32_t*>(s0 + k0 + 8);
                A2[kt][3] = *reinterpret_cast<const uint32_t*>(s8 + k0 + 8);
            }
        }
    }

    // bias fragments (bias depends on row j only; same for both D columns)
    float cb1a, cb1b, cb2a = 0.f, cb2b = 0.f;
    {
        int m = t1 * 16 + g;
        cb1a = (m < G3) ? bhh[m] : 0.f;
        cb1b = (m + 8 < G3) ? bhh[m + 8] : 0.f;
        if (has2) {
            int m2 = t2 * 16 + g;
            cb2a = (m2 < G3) ? bhh[m2] : 0.f;
            cb2b = (m2 + 8 < G3) ? bhh[m2 + 8] : 0.f;
        }
    }

    // gate-stage mapping: e = tid < 300 -> (row, jj)
    const int e = tid;
    const bool ge = (e < 2 * HH);
    const int row = (e < HH) ? 0 : 1;
    const int jj  = e - row * HH;

    __syncthreads();

    for (int s = 0; s < TT; ++s) {
        int t = dir ? (TT - 1 - s) : s;
        // prefetch gi for this step's gate stage (lands during MMA phase)
        float g_r = 0.f, g_z = 0.f, g_n = 0.f;
        if (ge) {
            size_t gbase = ((size_t)(row ? b1 : b0) * TT + t) * G3 + jj;
            g_r = gi[gbase]; g_z = gi[gbase + HH]; g_n = gi[gbase + 2 * HH];
        }

        // ---- MMA phase: gh = Whh x h + bias ----
        {
            float d1[4] = {cb1a, cb1a, cb1b, cb1b};
            float d2[4] = {cb2a, cb2a, cb2b, cb2b};
            #pragma unroll
            for (int kt = 0; kt < 10; ++kt) {
                uint32_t b0r = 0, b1r = 0;
                if (g < 2) {   // B column n = g; rows n>=2 are zero
                    const __half* hp = &h_s[g][kt * 16 + tig * 2];
                    b0r = *reinterpret_cast<const uint32_t*>(hp);
                    b1r = *reinterpret_cast<const uint32_t*>(hp + 8);
                }
                mma16816(d1, A1[kt], b0r, b1r);
                if (has2) mma16816(d2, A2[kt], b0r, b1r);
            }
            if (tig == 0) {    // lanes holding D columns 0,1 = batch rows 0,1
                int m = t1 * 16 + g;
                ghb2[m]     = make_float2(d1[0], d1[1]);
                ghb2[m + 8] = make_float2(d1[2], d1[3]);
                if (has2) {
                    int m2 = t2 * 16 + g;
                    ghb2[m2]     = make_float2(d2[0], d2[1]);
                    ghb2[m2 + 8] = make_float2(d2[2], d2[3]);
                }
            }
        }
        __syncthreads();

        // ---- gate phase ----
        if (ge) {
            const float* gb = reinterpret_cast<const float*>(ghb2);
            float hr = gb[jj * 2 + row];
            float hz = gb[(jj + HH) * 2 + row];
            float hn = gb[(jj + 2 * HH) * 2 + row];
            float rg = sigm(g_r + hr);
            float zg = sigm(g_z + hz);
            float ng = fast_tanh(g_n + rg * hn);
            float hp = __half2float(h_s[row][jj]);
            float hv = (1.f - zg) * ng + zg * hp;
            h_s[row][jj] = __float2half(hv);
            d_seq[((size_t)(row ? b1 : b0) * TT + t) * (2 * HH) + dir * HH + jj] = hv;
        }
        __syncthreads();
    }
    if (ge) {
        float hv = __half2float(h_s[row][jj]);
        d_hidden[(size_t)(row ? b1 : b0) * (2 * HH) + dir * HH + jj] = hv;
    }
}

// ---------------- context ----------------
__global__ void ctx_kernel(const float* __restrict__ Wattn) {
    int bk = blockIdx.x;
    int b = bk / KK, k = bk - b * KK;
    __shared__ float hs[2 * HH];
    int tid = threadIdx.x;
    if (tid < 2 * HH) hs[tid] = d_hidden[b * 2 * HH + tid];
    __syncthreads();
    if (tid < 2 * HH) {
        float acc = d_bias2[k * 2 * HH + tid];
        const float* w = Wattn + ((size_t)k * (CC + 2 * HH) + CC) * (2 * HH) + tid;
        #pragma unroll 4
        for (int c = 0; c < 2 * HH; ++c) acc += hs[c] * w[(size_t)c * (2 * HH)];
        d_context[((size_t)b * KK + k) * (2 * HH) + tid] = tanhf(acc);
    }
}

// ---------------- energy -> softmax(t) -> pooled ----------------
__global__ void pool_kernel() {
    int b = blockIdx.x;
    __shared__ float ctx[KK][2 * HH];
    __shared__ float en[TT][KK];
    int tid = threadIdx.x;              // 512
    int w = tid >> 5, lane = tid & 31;
    for (int i = tid; i < KK * 2 * HH; i += 512)
        ctx[i / (2 * HH)][i % (2 * HH)] = d_context[(size_t)b * KK * 2 * HH + i];
    __syncthreads();
    for (int t = w; t < TT; t += 16) {
        const float* srow = d_seq + ((size_t)b * TT + t) * (2 * HH);
        float pk[KK] = {0, 0, 0, 0, 0, 0};
        for (int d = lane; d < 2 * HH; d += 32) {
            float s = srow[d];
            #pragma unroll
            for (int k = 0; k < KK; ++k) pk[k] = fmaf(s, ctx[k][d], pk[k]);
        }
        #pragma unroll
        for (int k = 0; k < KK; ++k) {
            float v = pk[k];
            for (int off = 16; off; off >>= 1) v += __shfl_xor_sync(~0u, v, off);
            if (lane == 0) en[t][k] = v;
        }
    }
    __syncthreads();
    if (w < KK) {
        float mx = -1e30f;
        for (int t = lane; t < TT; t += 32) mx = fmaxf(mx, en[t][w]);
        for (int off = 16; off; off >>= 1) mx = fmaxf(mx, __shfl_xor_sync(~0u, mx, off));
        float sum = 0.f;
        for (int t = lane; t < TT; t += 32) { float e2 = __expf(en[t][w] - mx); en[t][w] = e2; sum += e2; }
        for (int off = 16; off; off >>= 1) sum += __shfl_xor_sync(~0u, sum, off);
        float inv = 1.f / sum;
        for (int t = lane; t < TT; t += 32) en[t][w] *= inv;
    }
    __syncthreads();
    for (int d = tid; d < 2 * HH; d += 512) {
        float acc[KK] = {0, 0, 0, 0, 0, 0};
        for (int t = 0; t < TT; ++t) {
            float s = d_seq[((size_t)b * TT + t) * (2 * HH) + d];
            #pragma unroll
            for (int k = 0; k < KK; ++k) acc[k] = fmaf(s, en[t][k], acc[k]);
        }
        #pragma unroll
        for (int k = 0; k < KK; ++k)
            d_pooled[((size_t)b * KK + k) * (2 * HH) + d] = acc[k];
    }
}

// ---------------- topic -> logits -> softmax ----------------
__global__ void topic_kernel(const float* __restrict__ Wtop, const float* __restrict__ btop,
                             const float* __restrict__ Wout, const float* __restrict__ bout,
                             float* __restrict__ out) {
    int b = blockIdx.x;
    __shared__ float ps[KK * 2 * HH];
    __shared__ float feats[KK * THD];
    __shared__ float lg[CLS];
    int tid = threadIdx.x;
    for (int i = tid; i < KK * 2 * HH; i += 128) ps[i] = d_pooled[(size_t)b * KK * 2 * HH + i];
    __syncthreads();
    if (tid < KK * THD) {
        int k = tid / THD, th = tid - k * THD;
        float acc = btop[tid];
        const float* wp = Wtop + (size_t)k * (2 * HH) * THD + th;
        #pragma unroll 4
        for (int d = 0; d < 2 * HH; ++d) acc += ps[k * 2 * HH + d] * wp[d * THD];
        feats[tid] = fmaxf(acc, 0.f);
    }
    __syncthreads();
    if (tid < CLS) {
        float acc = bout[tid];
        for (int e2 = 0; e2 < KK * THD; ++e2) acc += feats[e2] * Wout[e2 * CLS + tid];
        lg[tid] = acc;
    }
    __syncthreads();
    if (tid < CLS) {
        float mx = lg[0];
        #pragma unroll
        for (int c = 1; c < CLS; ++c) mx = fmaxf(mx, lg[c]);
        float sum = 0.f;
        #pragma unroll
        for (int c = 0; c < CLS; ++c) sum += __expf(lg[c] - mx);
        out[b * CLS + tid] = __expf(lg[tid] - mx) / sum;
    }
}

// ---------------- orthogonality regularizer ----------------
__global__ void reg_partial_kernel() {
    int b = blockIdx.x;
    __shared__ float cs[KK * 2 * HH];
    __shared__ float D[KK * KK];
    int tid = threadIdx.x;
    int w = tid >> 5, lane = tid & 31;
    for (int i = tid; i < KK * 2 * HH; i += 256) cs[i] = d_context[(size_t)b * KK * 2 * HH + i];
    __syncthreads();
    for (int p2 = w; p2 < KK * KK; p2 += 8) {
        int k = p2 / KK, j = p2 - k * KK;
        float v = 0.f;
        for (int d = lane; d < 2 * HH; d += 32) v += cs[k * 2 * HH + d] * cs[j * 2 * HH + d];
        for (int off = 16; off; off >>= 1) v += __shfl_xor_sync(~0u, v, off);
        if (lane == 0) D[p2] = v;
    }
    __syncthreads();
    if (tid == 0) {
        float nk[KK];
        #pragma unroll
        for (int k = 0; k < KK; ++k) nk[k] = fmaxf(sqrtf(D[k * KK + k]), 1e-12f);
        float S = 0.f;
        for (int k = 0; k < KK; ++k)
            for (int j = 0; j < KK; ++j) {
                float g = D[k * KK + j] / (nk[k] * nk[j]) - (k == j ? 1.f : 0.f);
                S += g * g;
            }
        d_regpart[b] = sqrtf(S);
    }
}

__global__ void reg_final_kernel(float* __restrict__ regout) {
    __shared__ float s[BB];
    int tid = threadIdx.x;
    s[tid] = d_regpart[tid];
    __syncthreads();
    for (int off = 64; off; off >>= 1) {
        if (tid < off) s[tid] += s[tid + off];
        __syncthreads();
    }
    if (tid == 0) *regout = s[0] / (float)BB;
}

// ---------------- launch ------------------------------------------------------------------
extern "C" void kernel_launch(void* const* d_in, const int* in_sizes, int n_in,
                              void* d_out, int out_size) {
    const float* x      = (const float*)d_in[0];
    const float* Wih_f  = (const float*)d_in[1];
    const float* Whh_f  = (const float*)d_in[2];
    const float* bih_f  = (const float*)d_in[3];
    const float* bhh_f  = (const float*)d_in[4];
    const float* Wih_b  = (const float*)d_in[5];
    const float* Whh_b  = (const float*)d_in[6];
    const float* bih_b  = (const float*)d_in[7];
    const float* bhh_b  = (const float*)d_in[8];
    const float* attn_c = (const float*)d_in[9];
    const float* Wattn  = (const float*)d_in[10];
    const float* battn  = (const float*)d_in[11];
    const float* Wtop   = (const float*)d_in[12];
    const float* btop   = (const float*)d_in[13];
    const float* Wout   = (const float*)d_in[14];
    const float* bout   = (const float*)d_in[15];
    float* out = (float*)d_out;

    prep_kernel<<<(2 * JPAD * KPAD2 + 255) / 256, 256>>>(Whh_f, Whh_b);
    const int npair = MM * (KP / 2) + 2 * 512 * (KP / 2);
    convert_kernel<<<(npair + 255) / 256, 256>>>(x, Wih_f, Wih_b);
    bias2_kernel<<<KK, 320>>>(attn_c, Wattn, battn);

    gemm_gi<<<dim3(8, 512, 2), 256>>>(bih_f, bih_b);

    scan_kernel<<<128, 512>>>(bhh_f, bhh_b);

    ctx_kernel<<<BB * KK, 320>>>(Wattn);
    pool_kernel<<<BB, 512>>>();
    topic_kernel<<<BB, 128>>>(Wtop, btop, Wout, bout, out);
    if (out_size > BB * CLS) {
        reg_partial_kernel<<<BB, 256>>>();
        reg_final_kernel<<<1, BB>>>(out + BB * CLS);
    }
}